// round 10
// baseline (speedup 1.0000x reference)
#include <cuda_runtime.h>
#include <cuda_fp16.h>
#include <cstddef>
#include <cstdint>

#define SEQ    2048
#define KDIM   1024

// ---------------------------------------------------------------------------
// Device scratch (no allocation allowed)
// ---------------------------------------------------------------------------
__device__ __half g_xh[4096 * 1024];                 // x fp16
__device__ __half g_wqt[1024 * 1024];                // W^T [N,K] fp16
__device__ __half g_wkt[256 * 1024];
__device__ __half g_wvt[256 * 1024];
__device__ __half g_wot[1024 * 1024];
__device__ __half g_qh[4096 * 1024];                 // Q RoPE'd, ×0.125·log2e
__device__ __half g_kh[4096 * 256];                  // K RoPE'd
__device__ __half g_vth[8 * 64 * 2048];              // V^T [(b*4+hk)][d][s]
__device__ __half g_oh[4096 * 1024];                 // attention out

// ---------------------------------------------------------------------------
// PTX helpers (architecture-generic; plain sm_103 target)
// ---------------------------------------------------------------------------
__device__ __forceinline__ void ldsm_x4(uint32_t r[4], uint32_t addr) {
    asm volatile("ldmatrix.sync.aligned.m8n8.x4.shared.b16 {%0,%1,%2,%3}, [%4];"
        : "=r"(r[0]), "=r"(r[1]), "=r"(r[2]), "=r"(r[3]) : "r"(addr));
}
__device__ __forceinline__ void mma16816(float c[4], const uint32_t a[4], const uint32_t b[2]) {
    asm volatile(
        "mma.sync.aligned.m16n8k16.row.col.f32.f16.f16.f32 "
        "{%0,%1,%2,%3}, {%4,%5,%6,%7}, {%8,%9}, {%0,%1,%2,%3};"
        : "+f"(c[0]), "+f"(c[1]), "+f"(c[2]), "+f"(c[3])
        : "r"(a[0]), "r"(a[1]), "r"(a[2]), "r"(a[3]), "r"(b[0]), "r"(b[1]));
}
__device__ __forceinline__ void cp16(uint32_t dst, const void* src) {
    asm volatile("cp.async.cg.shared.global [%0], [%1], 16;" :: "r"(dst), "l"(src));
}
__device__ __forceinline__ uint32_t pack_f16(float lo, float hi) {
    const __half2 h = __floats2half2_rn(lo, hi);
    return *reinterpret_cast<const uint32_t*>(&h);
}

// ---------------------------------------------------------------------------
// fp16 HMMA GEMM: C[M,N] = A[M,1024] @ B[N,1024]^T.
// OMODE: 0 fp32 out | 1 RoPE -> fp16 | 2 RoPE+0.125*log2e -> fp16 | 3 V^T fp16
// CTA 128x128, 8 warps (warp 64x32), K-chunk 64, THREE-stage cp.async,
// ONE __syncthreads per chunk. smem: 3 x 32 KB = 96 KB dynamic.
// ---------------------------------------------------------------------------
#define GSM_STAGE 32768
#define GSM_TOT   98304

template <int OMODE>
__device__ __forceinline__ void gemm_hmma(
    const __half* __restrict__ A, const __half* __restrict__ B,
    float* __restrict__ Cf, __half* __restrict__ Ch,
    int N, int brow, int bcol,
    const float* __restrict__ fc, const float* __restrict__ fs)
{
    extern __shared__ char gsm[];
    const uint32_t sb = (uint32_t)__cvta_generic_to_shared(gsm);

    const int tid  = threadIdx.x;
    const int wid  = tid >> 5;
    const int lane = tid & 31;
    const int m_base = (wid >> 2) * 64;
    const int n_base = (wid & 3) * 32;

    const int lrow = tid >> 1;                 // 128 rows, 2 thr/row
    const __half* Asrc = A + (size_t)(brow + lrow) * KDIM;
    const __half* Bsrc = B + (size_t)(bcol + lrow) * KDIM;

    float acc[4][4][4];
    #pragma unroll
    for (int mi = 0; mi < 4; ++mi)
        #pragma unroll
        for (int nj = 0; nj < 4; ++nj)
            #pragma unroll
            for (int e = 0; e < 4; ++e) acc[mi][nj][e] = 0.f;

    const int arow0 = (lane & 15);
    const int akoff = (lane >> 4);
    const int brw   = ((lane >> 4) << 3) + (lane & 7);
    const int bkoff = ((lane >> 3) & 1);

    auto load_chunk = [&](int st, int c) {
        const uint32_t stoff = sb + (uint32_t)(st * GSM_STAGE);
        #pragma unroll
        for (int j = 0; j < 4; ++j) {
            const int cc = (tid & 1) * 4 + j;
            const uint32_t sw = (uint32_t)(((cc ^ (lrow & 7)) << 4) + (lrow << 7));
            cp16(stoff +         sw, Asrc + c * 64 + cc * 8);
            cp16(stoff + 16384 + sw, Bsrc + c * 64 + cc * 8);
        }
        asm volatile("cp.async.commit_group;");
    };

    const int NCH = KDIM / 64;   // 16
    load_chunk(0, 0);
    load_chunk(1, 1);

    int st = 0;
    #pragma unroll 1
    for (int c = 0; c < NCH; ++c) {
        if (c + 1 < NCH) {
            asm volatile("cp.async.wait_group 1;");
        } else {
            asm volatile("cp.async.wait_group 0;");
        }
        __syncthreads();
        if (c + 2 < NCH) {
            int nst = st + 2; if (nst >= 3) nst -= 3;
            load_chunk(nst, c + 2);
        }
        const uint32_t stoff = sb + (uint32_t)(st * GSM_STAGE);

        #pragma unroll
        for (int kc = 0; kc < 4; ++kc) {
            uint32_t bf[4][2];
            #pragma unroll
            for (int g = 0; g < 2; ++g) {
                const int r = n_base + g * 16 + brw;
                const uint32_t ch = (uint32_t)((((2 * kc + bkoff) ^ (r & 7)) << 4) +
                                               (r << 7));
                uint32_t t4[4];
                ldsm_x4(t4, stoff + 16384 + ch);
                bf[g * 2][0] = t4[0]; bf[g * 2][1] = t4[1];
                bf[g * 2 + 1][0] = t4[2]; bf[g * 2 + 1][1] = t4[3];
            }
            #pragma unroll
            for (int mi = 0; mi < 4; ++mi) {
                const int r = m_base + mi * 16 + arow0;
                const uint32_t ch = (uint32_t)((((2 * kc + akoff) ^ (r & 7)) << 4) +
                                               (r << 7));
                uint32_t af[4];
                ldsm_x4(af, stoff + ch);
                #pragma unroll
                for (int nj = 0; nj < 4; ++nj)
                    mma16816(acc[mi][nj], af, bf[nj]);
            }
        }
        if (++st == 3) st = 0;
    }

    const int rbase = brow + m_base + (lane >> 2);
    const int cbase = bcol + n_base + (lane & 3) * 2;
    #pragma unroll
    for (int mi = 0; mi < 4; ++mi) {
        #pragma unroll
        for (int half = 0; half < 2; ++half) {
            const int r = rbase + mi * 16 + half * 8;
            const int srow = r & (SEQ - 1);
            #pragma unroll
            for (int nj = 0; nj < 4; ++nj) {
                const int col = cbase + nj * 8;
                float v0 = acc[mi][nj][half * 2];
                float v1 = acc[mi][nj][half * 2 + 1];
                if (OMODE == 1 || OMODE == 2) {
                    const int pair = (col & 63) >> 1;
                    const float cc = fc[srow * 32 + pair];
                    const float ss = fs[srow * 32 + pair];
                    float orv = v0 * cc - v1 * ss;
                    float oiv = v0 * ss + v1 * cc;
                    if (OMODE == 2) {
                        // 0.125 * log2(e): fold 1/sqrt(d) + exp2 conversion
                        orv *= 0.1803368801111244f; oiv *= 0.1803368801111244f;
                    }
                    const __half2 hv = __floats2half2_rn(orv, oiv);
                    *reinterpret_cast<__half2*>(Ch + (size_t)r * N + col) = hv;
                } else if (OMODE == 3) {
                    // V^T: dst[(b*4+hk)*64 + d][s]
                    const int b  = r >> 11;
                    const int s  = r & (SEQ - 1);
                    const int hk = col >> 6;
                    const int d  = col & 63;
                    __half* dst = Ch + ((size_t)((b * 4 + hk) * 64 + d)) * SEQ + s;
                    dst[0]   = __float2half(v0);
                    dst[SEQ] = __float2half(v1);
                } else {
                    *reinterpret_cast<float2*>(Cf + (size_t)r * N + col) = make_float2(v0, v1);
                }
            }
        }
    }
}

// Fused QKV: bx 0-7 Q (+RoPE+scale), 8-9 K (+RoPE), 10-11 V (->V^T)
__global__ void __launch_bounds__(256, 2) qkv_hmma_kernel(
    const float* __restrict__ fc, const float* __restrict__ fs)
{
    const int bx   = blockIdx.x;
    const int brow = blockIdx.y * 128;
    if (bx < 8)
        gemm_hmma<2>(g_xh, g_wqt, nullptr, g_qh, 1024, brow, bx * 128, fc, fs);
    else if (bx < 10)
        gemm_hmma<1>(g_xh, g_wkt, nullptr, g_kh, 256, brow, (bx - 8) * 128, fc, fs);
    else
        gemm_hmma<3>(g_xh, g_wvt, nullptr, g_vth, 256, brow, (bx - 10) * 128, nullptr, nullptr);
}

__global__ void __launch_bounds__(256, 2) oproj_hmma_kernel(float* __restrict__ out)
{
    gemm_hmma<0>(g_oh, g_wot, out, nullptr, 1024,
                 blockIdx.y * 128, blockIdx.x * 128, nullptr, nullptr);
}

// ---------------------------------------------------------------------------
// Fused prep: [0,4096) x->fp16 | then wq, wk, wv, wo transpose->fp16
// ---------------------------------------------------------------------------
__device__ __forceinline__ void wconv_body(
    const float* __restrict__ W, __half* __restrict__ T, int N, int n0, int k0)
{
    __shared__ float t[32][33];
    const int tx = threadIdx.x & 31, ty = threadIdx.x >> 5;
    #pragma unroll
    for (int i = 0; i < 32; i += 8)
        t[ty + i][tx] = W[(size_t)(k0 + ty + i) * N + n0 + tx];
    __syncthreads();
    #pragma unroll
    for (int i = 0; i < 32; i += 8)
        T[(size_t)(n0 + ty + i) * 1024 + k0 + tx] = __float2half(t[tx][ty + i]);
}

__global__ void __launch_bounds__(256) prep_kernel(
    const float* __restrict__ x,
    const float* __restrict__ wq, const float* __restrict__ wk,
    const float* __restrict__ wv, const float* __restrict__ wo)
{
    const int bid = blockIdx.x;
    if (bid < 4096) {
        const int i = bid * 256 + threadIdx.x;
        const float4 v = reinterpret_cast<const float4*>(x)[i];
        uint2 st;
        st.x = pack_f16(v.x, v.y);
        st.y = pack_f16(v.z, v.w);
        reinterpret_cast<uint2*>(g_xh)[i] = st;
    } else if (bid < 5120) {
        const int i = bid - 4096;
        wconv_body(wq, g_wqt, 1024, (i & 31) * 32, (i >> 5) * 32);
    } else if (bid < 5376) {
        const int i = bid - 5120;
        wconv_body(wk, g_wkt, 256, (i & 7) * 32, (i >> 3) * 32);
    } else if (bid < 5632) {
        const int i = bid - 5376;
        wconv_body(wv, g_wvt, 256, (i & 7) * 32, (i >> 3) * 32);
    } else {
        const int i = bid - 5632;
        wconv_body(wo, g_wot, 1024, (i & 31) * 32, (i >> 5) * 32);
    }
}

// ---------------------------------------------------------------------------
// Tensor-core flash attention (fp16, exp2 domain). CTA = 128 queries x (b,h).
// 8 warps x 16 query rows (256 threads). K-tiles of 64 keys.
// THREE-stage cp.async, ONE __syncthreads per tile.
// smem: Q 16K | 3 stages x (K 8K + V^T 8K) = 64 KB dynamic.
// ---------------------------------------------------------------------------
#define ASM_Q   0
#define ASM_ST  16384
#define ASM_TOT 65536

__global__ void __launch_bounds__(256, 2) attn_mma_kernel()
{
    extern __shared__ char asmem[];
    const uint32_t sb = (uint32_t)__cvta_generic_to_shared(asmem);
    const int tid = threadIdx.x, w = tid >> 5, lane = tid & 31;
    const int b = blockIdx.z, h = blockIdx.y;
    const int qt = (int)gridDim.x - 1 - blockIdx.x;   // heavy tiles first
    const int hk = h >> 2;
    const int q0 = qt * 128;
    const int ntiles = 2 * qt + 2;

    // --- Q tile load (once): 128 rows x 64 d ---
    {
        const int row = tid >> 1;
        const size_t qoff = (size_t)(b * SEQ + q0 + row) * 1024 + h * 64;
        #pragma unroll
        for (int j = 0; j < 4; ++j) {
            const int c = (tid & 1) * 4 + j;
            const uint32_t sw = (uint32_t)((c ^ (row & 7)) << 4) + (uint32_t)(row << 7);
            cp16(sb + ASM_Q + sw, g_qh + qoff + c * 8);
        }
        asm volatile("cp.async.commit_group;");
    }
    auto load_stage = [&](int st, int kt) {
        const int row = tid >> 2;                    // 64 rows
        const uint32_t so = sb + ASM_ST + (uint32_t)st * 16384;
        const size_t koff = (size_t)(b * SEQ + kt * 64 + row) * 256 + hk * 64;
        const size_t voff = (size_t)((b * 4 + hk) * 64 + row) * SEQ + kt * 64;
        #pragma unroll
        for (int i = 0; i < 2; ++i) {
            const int c = (tid & 3) * 2 + i;
            const uint32_t sw = (uint32_t)((c ^ (row & 7)) << 4) + (uint32_t)(row << 7);
            cp16(so +        sw, g_kh + koff + c * 8);
            cp16(so + 8192 + sw, g_vth + voff + c * 8);
        }
        asm volatile("cp.async.commit_group;");
    };
    load_stage(0, 0);
    load_stage(1, 1);

    const int arow = lane & 15, akoff = lane >> 4;
    const int brw  = ((lane >> 4) << 3) + (lane & 7);
    const int bkoff = (lane >> 3) & 1;

    // --- hoist Q fragments (Q group done; 2 stage groups may be pending) ---
    asm volatile("cp.async.wait_group 2;");
    __syncthreads();
    uint32_t qf[4][4];
    #pragma unroll
    for (int kc = 0; kc < 4; ++kc) {
        const int r = w * 16 + arow;
        const uint32_t ch = (uint32_t)(((2 * kc + akoff) ^ (r & 7)) << 4) +
                            (uint32_t)(r << 7);
        ldsm_x4(qf[kc], sb + ASM_Q + ch);
    }

    float o[8][4];
    #pragma unroll
    for (int nj = 0; nj < 8; ++nj)
        #pragma unroll
        for (int e = 0; e < 4; ++e) o[nj][e] = 0.f;
    float mrow[2] = {-1e30f, -1e30f};
    float lrow[2] = {0.f, 0.f};

    int st = 0;
    #pragma unroll 1
    for (int kt = 0; kt < ntiles; ++kt) {
        if (kt + 1 < ntiles) {
            asm volatile("cp.async.wait_group 1;");
        } else {
            asm volatile("cp.async.wait_group 0;");
        }
        __syncthreads();
        if (kt + 2 < ntiles) {
            int nst = st + 2; if (nst >= 3) nst -= 3;
            load_stage(nst, kt + 2);
        }
        const uint32_t so = sb + ASM_ST + (uint32_t)st * 16384;

        // ---- S = Q @ K^T (scores already in log2 domain) ----
        float sc[8][4];
        #pragma unroll
        for (int nj = 0; nj < 8; ++nj)
            #pragma unroll
            for (int e = 0; e < 4; ++e) sc[nj][e] = 0.f;

        #pragma unroll
        for (int kc = 0; kc < 4; ++kc) {
            uint32_t kb[8][2];
            #pragma unroll
            for (int g = 0; g < 4; ++g) {
                const int r = g * 16 + brw;
                const uint32_t ch = (uint32_t)(((2 * kc + bkoff) ^ (r & 7)) << 4) +
                                    (uint32_t)(r << 7);
                uint32_t t4[4];
                ldsm_x4(t4, so + ch);
                kb[g * 2][0] = t4[0]; kb[g * 2][1] = t4[1];
                kb[g * 2 + 1][0] = t4[2]; kb[g * 2 + 1][1] = t4[3];
            }
            #pragma unroll
            for (int nj = 0; nj < 8; ++nj)
                mma16816(sc[nj], qf[kc], kb[nj]);
        }

        // ---- causal mask (partial tiles only) ----
        const int qwbase = q0 + w * 16;
        if (kt * 64 + 63 > qwbase) {
            const int jb = kt * 64 + (lane & 3) * 2;
            const int qb = qwbase + (lane >> 2);
            #pragma unroll
            for (int nj = 0; nj < 8; ++nj)
                #pragma unroll
                for (int e = 0; e < 4; ++e) {
                    const int j = jb + nj * 8 + (e & 1);
                    const int q = qb + ((e >> 1) << 3);
                    if (j > q) sc[nj][e] = -1e30f;
                }
        }

        // ---- online softmax (base-2) ----
        float tm[2] = {-1e30f, -1e30f};
        #pragma unroll
        for (int nj = 0; nj < 8; ++nj)
            #pragma unroll
            for (int e = 0; e < 4; ++e)
                tm[e >> 1] = fmaxf(tm[e >> 1], sc[nj][e]);
        float alpha[2];
        #pragma unroll
        for (int ri = 0; ri < 2; ++ri) {
            tm[ri] = fmaxf(tm[ri], __shfl_xor_sync(0xffffffffu, tm[ri], 1));
            tm[ri] = fmaxf(tm[ri], __shfl_xor_sync(0xffffffffu, tm[ri], 2));
            const float nm = fmaxf(mrow[ri], tm[ri]);
            alpha[ri] = exp2f(mrow[ri] - nm);
            mrow[ri] = nm;
            lrow[ri] *= alpha[ri];
        }
        const bool chg = (alpha[0] < 1.f) || (alpha[1] < 1.f);
        if (__any_sync(0xffffffffu, chg)) {
            #pragma unroll
            for (int nj = 0; nj < 8; ++nj) {
                o[nj][0] *= alpha[0]; o[nj][1] *= alpha[0];
                o[nj][2] *= alpha[1]; o[nj][3] *= alpha[1];
            }
        }
        #pragma unroll
        for (int nj = 0; nj < 8; ++nj)
            #pragma unroll
            for (int e = 0; e < 4; ++e) {
                const float p = exp2f(sc[nj][e] - mrow[e >> 1]);
                sc[nj][e] = p;
                lrow[e >> 1] += p;
            }

        // ---- O += P @ V ----
        #pragma unroll
        for (int kc = 0; kc < 4; ++kc) {
            uint32_t ap[4];
            {
                const float* s0 = sc[2 * kc];
                const float* s1 = sc[2 * kc + 1];
                ap[0] = pack_f16(s0[0], s0[1]);
                ap[1] = pack_f16(s0[2], s0[3]);
                ap[2] = pack_f16(s1[0], s1[1]);
                ap[3] = pack_f16(s1[2], s1[3]);
            }
            uint32_t vb[8][2];
            #pragma unroll
            for (int g = 0; g < 4; ++g) {
                const int r = g * 16 + brw;
                const uint32_t ch = (uint32_t)(((2 * kc + bkoff) ^ (r & 7)) << 4) +
                                    (uint32_t)(r << 7);
                uint32_t t4[4];
                ldsm_x4(t4, so + 8192 + ch);
                vb[g * 2][0] = t4[0]; vb[g * 2][1] = t4[1];
                vb[g * 2 + 1][0] = t4[2]; vb[g * 2 + 1][1] = t4[3];
            }
            #pragma unroll
            for (int nj = 0; nj < 8; ++nj)
                mma16816(o[nj], ap, vb[nj]);
        }
        if (++st == 3) st = 0;
    }

    // ---- epilogue: normalize + write fp16 ----
    float linv[2];
    #pragma unroll
    for (int ri = 0; ri < 2; ++ri) {
        float l = lrow[ri];
        l += __shfl_xor_sync(0xffffffffu, l, 1);
        l += __shfl_xor_sync(0xffffffffu, l, 2);
        linv[ri] = 1.0f / l;
    }
    #pragma unroll
    for (int half = 0; half < 2; ++half) {
        const int rloc = w * 16 + (lane >> 2) + half * 8;
        const size_t rg = (size_t)(b * SEQ + q0 + rloc) * 1024 + h * 64;
        const float inv = linv[half];
        #pragma unroll
        for (int nj = 0; nj < 8; ++nj) {
            const int col = nj * 8 + (lane & 3) * 2;
            const __half2 hv = __floats2half2_rn(o[nj][half * 2] * inv,
                                                 o[nj][half * 2 + 1] * inv);
            *reinterpret_cast<__half2*>(g_oh + rg + col) = hv;
        }
    }
}

// ---------------------------------------------------------------------------
// Inputs: x, start_pos, freqs_cos, freqs_sin, mask, wq, wk, wv, wo
// ---------------------------------------------------------------------------
extern "C" void kernel_launch(void* const* d_in, const int* in_sizes, int n_in,
                              void* d_out, int out_size)
{
    const float* x  = (const float*)d_in[0];
    const float* fc = (const float*)d_in[2];
    const float* fs = (const float*)d_in[3];
    const float* wq = (const float*)d_in[5];
    const float* wk = (const float*)d_in[6];
    const float* wv = (const float*)d_in[7];
    const float* wo = (const float*)d_in[8];
    float* out = (float*)d_out;

    cudaFuncSetAttribute(qkv_hmma_kernel,
                         cudaFuncAttributeMaxDynamicSharedMemorySize, GSM_TOT);
    cudaFuncSetAttribute(oproj_hmma_kernel,
                         cudaFuncAttributeMaxDynamicSharedMemorySize, GSM_TOT);
    cudaFuncSetAttribute(attn_mma_kernel,
                         cudaFuncAttributeMaxDynamicSharedMemorySize, ASM_TOT);

    // Fused prep: x -> fp16; weights -> transposed fp16
    prep_kernel<<<6656, 256>>>(x, wq, wk, wv, wo);
    // QKV projection (fp16 HMMA; Q/K RoPE'd fp16; V written transposed)
    qkv_hmma_kernel<<<dim3(12, 32), 256, GSM_TOT>>>(fc, fs);
    // Tensor-core flash attention (256 thr, 8 warps x 16 rows)
    attn_mma_kernel<<<dim3(16, 16, 2), 256, ASM_TOT>>>();
    // Output projection -> d_out (fp32)
    oproj_hmma_kernel<<<dim3(8, 32), 256, GSM_TOT>>>(out);
}

// round 11
// speedup vs baseline: 1.5153x; 1.5153x over previous
#include <cuda_runtime.h>
#include <cuda_fp16.h>
#include <cstddef>
#include <cstdint>

#define SEQ    2048
#define KDIM   1024

// ---------------------------------------------------------------------------
// Device scratch (no allocation allowed)
// ---------------------------------------------------------------------------
__device__ __half g_xh[4096 * 1024];                 // x fp16
__device__ __half g_wqt[1024 * 1024];                // W^T [N,K] fp16
__device__ __half g_wkt[256 * 1024];
__device__ __half g_wvt[256 * 1024];
__device__ __half g_wot[1024 * 1024];
__device__ __half g_qh[4096 * 1024];                 // Q RoPE'd, ×0.125·log2e
__device__ __half g_kh[4096 * 256];                  // K RoPE'd
__device__ __half g_vth[8 * 64 * 2048];              // V^T [(b*4+hk)][d][s]
__device__ __half g_oh[4096 * 1024];                 // attention out

// ---------------------------------------------------------------------------
// PTX helpers (architecture-generic; plain sm_103 target)
// ---------------------------------------------------------------------------
__device__ __forceinline__ void ldsm_x4(uint32_t r[4], uint32_t addr) {
    asm volatile("ldmatrix.sync.aligned.m8n8.x4.shared.b16 {%0,%1,%2,%3}, [%4];"
        : "=r"(r[0]), "=r"(r[1]), "=r"(r[2]), "=r"(r[3]) : "r"(addr));
}
__device__ __forceinline__ void mma16816(float c[4], const uint32_t a[4], const uint32_t b[2]) {
    asm volatile(
        "mma.sync.aligned.m16n8k16.row.col.f32.f16.f16.f32 "
        "{%0,%1,%2,%3}, {%4,%5,%6,%7}, {%8,%9}, {%0,%1,%2,%3};"
        : "+f"(c[0]), "+f"(c[1]), "+f"(c[2]), "+f"(c[3])
        : "r"(a[0]), "r"(a[1]), "r"(a[2]), "r"(a[3]), "r"(b[0]), "r"(b[1]));
}
__device__ __forceinline__ void cp16(uint32_t dst, const void* src) {
    asm volatile("cp.async.cg.shared.global [%0], [%1], 16;" :: "r"(dst), "l"(src));
}
__device__ __forceinline__ uint32_t pack_f16(float lo, float hi) {
    const __half2 h = __floats2half2_rn(lo, hi);
    return *reinterpret_cast<const uint32_t*>(&h);
}

// ---------------------------------------------------------------------------
// fp16 HMMA GEMM: C[M,N] = A[M,1024] @ B[N,1024]^T.
// OMODE: 0 fp32 out | 1 RoPE -> fp16 | 2 RoPE+0.125*log2e -> fp16 | 3 V^T fp16
// CTA 128x128, 8 warps (warp 64x32), K-chunk 64, cp.async double buffer
// (round-9 structure: next load issued BEFORE wait_group — load-bearing).
// A-fragment ldsm fully batched per kc for load-level parallelism.
// smem: 2 stages x (A 16K + B 16K) = 64 KB dynamic.
// ---------------------------------------------------------------------------
#define GSM_STAGE 32768
#define GSM_TOT   65536

template <int OMODE>
__device__ __forceinline__ void gemm_hmma(
    const __half* __restrict__ A, const __half* __restrict__ B,
    float* __restrict__ Cf, __half* __restrict__ Ch,
    int N, int brow, int bcol,
    const float* __restrict__ fc, const float* __restrict__ fs)
{
    extern __shared__ char gsm[];
    const uint32_t sb = (uint32_t)__cvta_generic_to_shared(gsm);

    const int tid  = threadIdx.x;
    const int wid  = tid >> 5;
    const int lane = tid & 31;
    const int m_base = (wid >> 2) * 64;
    const int n_base = (wid & 3) * 32;

    const int lrow = tid >> 1;                 // 128 rows, 2 thr/row
    const __half* Asrc = A + (size_t)(brow + lrow) * KDIM;
    const __half* Bsrc = B + (size_t)(bcol + lrow) * KDIM;

    float acc[4][4][4];
    #pragma unroll
    for (int mi = 0; mi < 4; ++mi)
        #pragma unroll
        for (int nj = 0; nj < 4; ++nj)
            #pragma unroll
            for (int e = 0; e < 4; ++e) acc[mi][nj][e] = 0.f;

    const int arow0 = (lane & 15);
    const int akoff = (lane >> 4);
    const int brw   = ((lane >> 4) << 3) + (lane & 7);
    const int bkoff = ((lane >> 3) & 1);

    auto load_chunk = [&](int st, int c) {
        const uint32_t stoff = sb + (uint32_t)(st * GSM_STAGE);
        #pragma unroll
        for (int j = 0; j < 4; ++j) {
            const int cc = (tid & 1) * 4 + j;
            const uint32_t sw = (uint32_t)(((cc ^ (lrow & 7)) << 4) + (lrow << 7));
            cp16(stoff +         sw, Asrc + c * 64 + cc * 8);
            cp16(stoff + 16384 + sw, Bsrc + c * 64 + cc * 8);
        }
        asm volatile("cp.async.commit_group;");
    };

    const int NCH = KDIM / 64;   // 16
    load_chunk(0, 0);

    #pragma unroll 1
    for (int c = 0; c < NCH; ++c) {
        const int cur = c & 1;
        if (c + 1 < NCH) {
            load_chunk(cur ^ 1, c + 1);
            asm volatile("cp.async.wait_group 1;");
        } else {
            asm volatile("cp.async.wait_group 0;");
        }
        __syncthreads();
        const uint32_t stoff = sb + (uint32_t)(cur * GSM_STAGE);

        #pragma unroll
        for (int kc = 0; kc < 4; ++kc) {
            uint32_t bf[4][2];
            #pragma unroll
            for (int g = 0; g < 2; ++g) {
                const int r = n_base + g * 16 + brw;
                const uint32_t ch = (uint32_t)((((2 * kc + bkoff) ^ (r & 7)) << 4) +
                                               (r << 7));
                uint32_t t4[4];
                ldsm_x4(t4, stoff + 16384 + ch);
                bf[g * 2][0] = t4[0]; bf[g * 2][1] = t4[1];
                bf[g * 2 + 1][0] = t4[2]; bf[g * 2 + 1][1] = t4[3];
            }
            // batch ALL A-fragment loads before the MMA block (MLP)
            uint32_t af[4][4];
            #pragma unroll
            for (int mi = 0; mi < 4; ++mi) {
                const int r = m_base + mi * 16 + arow0;
                const uint32_t ch = (uint32_t)((((2 * kc + akoff) ^ (r & 7)) << 4) +
                                               (r << 7));
                ldsm_x4(af[mi], stoff + ch);
            }
            #pragma unroll
            for (int mi = 0; mi < 4; ++mi)
                #pragma unroll
                for (int nj = 0; nj < 4; ++nj)
                    mma16816(acc[mi][nj], af[mi], bf[nj]);
        }
        __syncthreads();
    }

    const int rbase = brow + m_base + (lane >> 2);
    const int cbase = bcol + n_base + (lane & 3) * 2;
    #pragma unroll
    for (int mi = 0; mi < 4; ++mi) {
        #pragma unroll
        for (int half = 0; half < 2; ++half) {
            const int r = rbase + mi * 16 + half * 8;
            const int srow = r & (SEQ - 1);
            #pragma unroll
            for (int nj = 0; nj < 4; ++nj) {
                const int col = cbase + nj * 8;
                float v0 = acc[mi][nj][half * 2];
                float v1 = acc[mi][nj][half * 2 + 1];
                if (OMODE == 1 || OMODE == 2) {
                    const int pair = (col & 63) >> 1;
                    const float cc = fc[srow * 32 + pair];
                    const float ss = fs[srow * 32 + pair];
                    float orv = v0 * cc - v1 * ss;
                    float oiv = v0 * ss + v1 * cc;
                    if (OMODE == 2) {
                        // 0.125 * log2(e): fold 1/sqrt(d) + exp2 conversion
                        orv *= 0.1803368801111244f; oiv *= 0.1803368801111244f;
                    }
                    const __half2 hv = __floats2half2_rn(orv, oiv);
                    *reinterpret_cast<__half2*>(Ch + (size_t)r * N + col) = hv;
                } else if (OMODE == 3) {
                    // V^T: dst[(b*4+hk)*64 + d][s]
                    const int b  = r >> 11;
                    const int s  = r & (SEQ - 1);
                    const int hk = col >> 6;
                    const int d  = col & 63;
                    __half* dst = Ch + ((size_t)((b * 4 + hk) * 64 + d)) * SEQ + s;
                    dst[0]   = __float2half(v0);
                    dst[SEQ] = __float2half(v1);
                } else {
                    *reinterpret_cast<float2*>(Cf + (size_t)r * N + col) = make_float2(v0, v1);
                }
            }
        }
    }
}

// Fused QKV: bx 0-7 Q (+RoPE+scale), 8-9 K (+RoPE), 10-11 V (->V^T)
__global__ void __launch_bounds__(256, 2) qkv_hmma_kernel(
    const float* __restrict__ fc, const float* __restrict__ fs)
{
    const int bx   = blockIdx.x;
    const int brow = blockIdx.y * 128;
    if (bx < 8)
        gemm_hmma<2>(g_xh, g_wqt, nullptr, g_qh, 1024, brow, bx * 128, fc, fs);
    else if (bx < 10)
        gemm_hmma<1>(g_xh, g_wkt, nullptr, g_kh, 256, brow, (bx - 8) * 128, fc, fs);
    else
        gemm_hmma<3>(g_xh, g_wvt, nullptr, g_vth, 256, brow, (bx - 10) * 128, nullptr, nullptr);
}

__global__ void __launch_bounds__(256, 2) oproj_hmma_kernel(float* __restrict__ out)
{
    gemm_hmma<0>(g_oh, g_wot, out, nullptr, 1024,
                 blockIdx.y * 128, blockIdx.x * 128, nullptr, nullptr);
}

// ---------------------------------------------------------------------------
// Fused prep: [0,4096) x->fp16 | then wq, wk, wv, wo transpose->fp16
// ---------------------------------------------------------------------------
__device__ __forceinline__ void wconv_body(
    const float* __restrict__ W, __half* __restrict__ T, int N, int n0, int k0)
{
    __shared__ float t[32][33];
    const int tx = threadIdx.x & 31, ty = threadIdx.x >> 5;
    #pragma unroll
    for (int i = 0; i < 32; i += 8)
        t[ty + i][tx] = W[(size_t)(k0 + ty + i) * N + n0 + tx];
    __syncthreads();
    #pragma unroll
    for (int i = 0; i < 32; i += 8)
        T[(size_t)(n0 + ty + i) * 1024 + k0 + tx] = __float2half(t[tx][ty + i]);
}

__global__ void __launch_bounds__(256) prep_kernel(
    const float* __restrict__ x,
    const float* __restrict__ wq, const float* __restrict__ wk,
    const float* __restrict__ wv, const float* __restrict__ wo)
{
    const int bid = blockIdx.x;
    if (bid < 4096) {
        const int i = bid * 256 + threadIdx.x;
        const float4 v = reinterpret_cast<const float4*>(x)[i];
        uint2 st;
        st.x = pack_f16(v.x, v.y);
        st.y = pack_f16(v.z, v.w);
        reinterpret_cast<uint2*>(g_xh)[i] = st;
    } else if (bid < 5120) {
        const int i = bid - 4096;
        wconv_body(wq, g_wqt, 1024, (i & 31) * 32, (i >> 5) * 32);
    } else if (bid < 5376) {
        const int i = bid - 5120;
        wconv_body(wk, g_wkt, 256, (i & 7) * 32, (i >> 3) * 32);
    } else if (bid < 5632) {
        const int i = bid - 5376;
        wconv_body(wv, g_wvt, 256, (i & 7) * 32, (i >> 3) * 32);
    } else {
        const int i = bid - 5632;
        wconv_body(wo, g_wot, 1024, (i & 31) * 32, (i >> 5) * 32);
    }
}

// ---------------------------------------------------------------------------
// Tensor-core flash attention (fp16, exp2 domain). CTA = 128 queries x (b,h).
// 8 warps x 16 query rows (256 threads). K-tiles of 64 keys,
// double-buffered cp.async (round-9 structure, byte-identical).
// smem: Q 16K | stage{0,1}: K 8K + V^T 8K   (48 KB dynamic)
// ---------------------------------------------------------------------------
#define ASM_Q   0
#define ASM_ST  16384
#define ASM_TOT 49152

__global__ void __launch_bounds__(256, 2) attn_mma_kernel()
{
    extern __shared__ char asmem[];
    const uint32_t sb = (uint32_t)__cvta_generic_to_shared(asmem);
    const int tid = threadIdx.x, w = tid >> 5, lane = tid & 31;
    const int b = blockIdx.z, h = blockIdx.y;
    const int qt = (int)gridDim.x - 1 - blockIdx.x;   // heavy tiles first
    const int hk = h >> 2;
    const int q0 = qt * 128;
    const int ntiles = 2 * qt + 2;

    // --- Q tile load (once): 128 rows x 64 d ---
    {
        const int row = tid >> 1;
        const size_t qoff = (size_t)(b * SEQ + q0 + row) * 1024 + h * 64;
        #pragma unroll
        for (int j = 0; j < 4; ++j) {
            const int c = (tid & 1) * 4 + j;
            const uint32_t sw = (uint32_t)((c ^ (row & 7)) << 4) + (uint32_t)(row << 7);
            cp16(sb + ASM_Q + sw, g_qh + qoff + c * 8);
        }
        asm volatile("cp.async.commit_group;");
    }
    auto load_stage = [&](int st, int kt) {
        const int row = tid >> 2;                    // 64 rows
        const uint32_t so = sb + ASM_ST + (uint32_t)st * 16384;
        const size_t koff = (size_t)(b * SEQ + kt * 64 + row) * 256 + hk * 64;
        const size_t voff = (size_t)((b * 4 + hk) * 64 + row) * SEQ + kt * 64;
        #pragma unroll
        for (int i = 0; i < 2; ++i) {
            const int c = (tid & 3) * 2 + i;
            const uint32_t sw = (uint32_t)((c ^ (row & 7)) << 4) + (uint32_t)(row << 7);
            cp16(so +        sw, g_kh + koff + c * 8);
            cp16(so + 8192 + sw, g_vth + voff + c * 8);
        }
        asm volatile("cp.async.commit_group;");
    };
    load_stage(0, 0);

    const int arow = lane & 15, akoff = lane >> 4;
    const int brw  = ((lane >> 4) << 3) + (lane & 7);
    const int bkoff = (lane >> 3) & 1;

    // --- hoist Q fragments (warp owns rows w*16 .. w*16+15) ---
    asm volatile("cp.async.wait_group 1;");
    __syncthreads();
    uint32_t qf[4][4];
    #pragma unroll
    for (int kc = 0; kc < 4; ++kc) {
        const int r = w * 16 + arow;
        const uint32_t ch = (uint32_t)(((2 * kc + akoff) ^ (r & 7)) << 4) +
                            (uint32_t)(r << 7);
        ldsm_x4(qf[kc], sb + ASM_Q + ch);
    }

    float o[8][4];
    #pragma unroll
    for (int nj = 0; nj < 8; ++nj)
        #pragma unroll
        for (int e = 0; e < 4; ++e) o[nj][e] = 0.f;
    float mrow[2] = {-1e30f, -1e30f};
    float lrow[2] = {0.f, 0.f};

    #pragma unroll 1
    for (int kt = 0; kt < ntiles; ++kt) {
        const int st = kt & 1;
        if (kt + 1 < ntiles) {
            load_stage(st ^ 1, kt + 1);
            asm volatile("cp.async.wait_group 1;");
        } else {
            asm volatile("cp.async.wait_group 0;");
        }
        __syncthreads();
        const uint32_t so = sb + ASM_ST + (uint32_t)st * 16384;

        // ---- S = Q @ K^T (scores already in log2 domain) ----
        float sc[8][4];
        #pragma unroll
        for (int nj = 0; nj < 8; ++nj)
            #pragma unroll
            for (int e = 0; e < 4; ++e) sc[nj][e] = 0.f;

        #pragma unroll
        for (int kc = 0; kc < 4; ++kc) {
            uint32_t kb[8][2];
            #pragma unroll
            for (int g = 0; g < 4; ++g) {
                const int r = g * 16 + brw;
                const uint32_t ch = (uint32_t)(((2 * kc + bkoff) ^ (r & 7)) << 4) +
                                    (uint32_t)(r << 7);
                uint32_t t4[4];
                ldsm_x4(t4, so + ch);
                kb[g * 2][0] = t4[0]; kb[g * 2][1] = t4[1];
                kb[g * 2 + 1][0] = t4[2]; kb[g * 2 + 1][1] = t4[3];
            }
            #pragma unroll
            for (int nj = 0; nj < 8; ++nj)
                mma16816(sc[nj], qf[kc], kb[nj]);
        }

        // ---- causal mask (partial tiles only) ----
        const int qwbase = q0 + w * 16;
        if (kt * 64 + 63 > qwbase) {
            const int jb = kt * 64 + (lane & 3) * 2;
            const int qb = qwbase + (lane >> 2);
            #pragma unroll
            for (int nj = 0; nj < 8; ++nj)
                #pragma unroll
                for (int e = 0; e < 4; ++e) {
                    const int j = jb + nj * 8 + (e & 1);
                    const int q = qb + ((e >> 1) << 3);
                    if (j > q) sc[nj][e] = -1e30f;
                }
        }

        // ---- online softmax (base-2) ----
        float tm[2] = {-1e30f, -1e30f};
        #pragma unroll
        for (int nj = 0; nj < 8; ++nj)
            #pragma unroll
            for (int e = 0; e < 4; ++e)
                tm[e >> 1] = fmaxf(tm[e >> 1], sc[nj][e]);
        float alpha[2];
        #pragma unroll
        for (int ri = 0; ri < 2; ++ri) {
            tm[ri] = fmaxf(tm[ri], __shfl_xor_sync(0xffffffffu, tm[ri], 1));
            tm[ri] = fmaxf(tm[ri], __shfl_xor_sync(0xffffffffu, tm[ri], 2));
            const float nm = fmaxf(mrow[ri], tm[ri]);
            alpha[ri] = exp2f(mrow[ri] - nm);
            mrow[ri] = nm;
            lrow[ri] *= alpha[ri];
        }
        const bool chg = (alpha[0] < 1.f) || (alpha[1] < 1.f);
        if (__any_sync(0xffffffffu, chg)) {
            #pragma unroll
            for (int nj = 0; nj < 8; ++nj) {
                o[nj][0] *= alpha[0]; o[nj][1] *= alpha[0];
                o[nj][2] *= alpha[1]; o[nj][3] *= alpha[1];
            }
        }
        #pragma unroll
        for (int nj = 0; nj < 8; ++nj)
            #pragma unroll
            for (int e = 0; e < 4; ++e) {
                const float p = exp2f(sc[nj][e] - mrow[e >> 1]);
                sc[nj][e] = p;
                lrow[e >> 1] += p;
            }

        // ---- O += P @ V ----
        #pragma unroll
        for (int kc = 0; kc < 4; ++kc) {
            uint32_t ap[4];
            {
                const float* s0 = sc[2 * kc];
                const float* s1 = sc[2 * kc + 1];
                ap[0] = pack_f16(s0[0], s0[1]);
                ap[1] = pack_f16(s0[2], s0[3]);
                ap[2] = pack_f16(s1[0], s1[1]);
                ap[3] = pack_f16(s1[2], s1[3]);
            }
            uint32_t vb[8][2];
            #pragma unroll
            for (int g = 0; g < 4; ++g) {
                const int r = g * 16 + brw;
                const uint32_t ch = (uint32_t)(((2 * kc + bkoff) ^ (r & 7)) << 4) +
                                    (uint32_t)(r << 7);
                uint32_t t4[4];
                ldsm_x4(t4, so + 8192 + ch);
                vb[g * 2][0] = t4[0]; vb[g * 2][1] = t4[1];
                vb[g * 2 + 1][0] = t4[2]; vb[g * 2 + 1][1] = t4[3];
            }
            #pragma unroll
            for (int nj = 0; nj < 8; ++nj)
                mma16816(o[nj], ap, vb[nj]);
        }
        __syncthreads();
    }

    // ---- epilogue: normalize + write fp16 ----
    float linv[2];
    #pragma unroll
    for (int ri = 0; ri < 2; ++ri) {
        float l = lrow[ri];
        l += __shfl_xor_sync(0xffffffffu, l, 1);
        l += __shfl_xor_sync(0xffffffffu, l, 2);
        linv[ri] = 1.0f / l;
    }
    #pragma unroll
    for (int half = 0; half < 2; ++half) {
        const int rloc = w * 16 + (lane >> 2) + half * 8;
        const size_t rg = (size_t)(b * SEQ + q0 + rloc) * 1024 + h * 64;
        const float inv = linv[half];
        #pragma unroll
        for (int nj = 0; nj < 8; ++nj) {
            const int col = nj * 8 + (lane & 3) * 2;
            const __half2 hv = __floats2half2_rn(o[nj][half * 2] * inv,
                                                 o[nj][half * 2 + 1] * inv);
            *reinterpret_cast<__half2*>(g_oh + rg + col) = hv;
        }
    }
}

// ---------------------------------------------------------------------------
// Inputs: x, start_pos, freqs_cos, freqs_sin, mask, wq, wk, wv, wo
// ---------------------------------------------------------------------------
extern "C" void kernel_launch(void* const* d_in, const int* in_sizes, int n_in,
                              void* d_out, int out_size)
{
    const float* x  = (const float*)d_in[0];
    const float* fc = (const float*)d_in[2];
    const float* fs = (const float*)d_in[3];
    const float* wq = (const float*)d_in[5];
    const float* wk = (const float*)d_in[6];
    const float* wv = (const float*)d_in[7];
    const float* wo = (const float*)d_in[8];
    float* out = (float*)d_out;

    cudaFuncSetAttribute(qkv_hmma_kernel,
                         cudaFuncAttributeMaxDynamicSharedMemorySize, GSM_TOT);
    cudaFuncSetAttribute(oproj_hmma_kernel,
                         cudaFuncAttributeMaxDynamicSharedMemorySize, GSM_TOT);
    cudaFuncSetAttribute(attn_mma_kernel,
                         cudaFuncAttributeMaxDynamicSharedMemorySize, ASM_TOT);

    // Fused prep: x -> fp16; weights -> transposed fp16
    prep_kernel<<<6656, 256>>>(x, wq, wk, wv, wo);
    // QKV projection (fp16 HMMA; Q/K RoPE'd fp16; V written transposed)
    qkv_hmma_kernel<<<dim3(12, 32), 256, GSM_TOT>>>(fc, fs);
    // Tensor-core flash attention (256 thr, 8 warps x 16 rows)
    attn_mma_kernel<<<dim3(16, 16, 2), 256, ASM_TOT>>>();
    // Output projection -> d_out (fp32)
    oproj_hmma_kernel<<<dim3(8, 32), 256, GSM_TOT>>>(out);
}

// round 12
// speedup vs baseline: 1.5643x; 1.0323x over previous
#include <cuda_runtime.h>
#include <cuda_fp16.h>
#include <cstddef>
#include <cstdint>

#define SEQ    2048
#define KDIM   1024

// ---------------------------------------------------------------------------
// Device scratch (no allocation allowed)
// ---------------------------------------------------------------------------
__device__ __half g_xh[4096 * 1024];                 // x fp16
__device__ __half g_wqt[1024 * 1024];                // W^T [N,K] fp16
__device__ __half g_wkt[256 * 1024];
__device__ __half g_wvt[256 * 1024];
__device__ __half g_wot[1024 * 1024];
__device__ __half g_qh[4096 * 1024];                 // Q RoPE'd, ×0.125·log2e
__device__ __half g_kh[4096 * 256];                  // K RoPE'd
__device__ __half g_vth[8 * 64 * 2048];              // V^T [(b*4+hk)][d][s]
__device__ __half g_oh[4096 * 1024];                 // attention out

// ---------------------------------------------------------------------------
// PTX helpers (architecture-generic; plain sm_103 target)
// ---------------------------------------------------------------------------
__device__ __forceinline__ void ldsm_x4(uint32_t r[4], uint32_t addr) {
    asm volatile("ldmatrix.sync.aligned.m8n8.x4.shared.b16 {%0,%1,%2,%3}, [%4];"
        : "=r"(r[0]), "=r"(r[1]), "=r"(r[2]), "=r"(r[3]) : "r"(addr));
}
__device__ __forceinline__ void mma16816(float c[4], const uint32_t a[4], const uint32_t b[2]) {
    asm volatile(
        "mma.sync.aligned.m16n8k16.row.col.f32.f16.f16.f32 "
        "{%0,%1,%2,%3}, {%4,%5,%6,%7}, {%8,%9}, {%0,%1,%2,%3};"
        : "+f"(c[0]), "+f"(c[1]), "+f"(c[2]), "+f"(c[3])
        : "r"(a[0]), "r"(a[1]), "r"(a[2]), "r"(a[3]), "r"(b[0]), "r"(b[1]));
}
__device__ __forceinline__ void cp16(uint32_t dst, const void* src) {
    asm volatile("cp.async.cg.shared.global [%0], [%1], 16;" :: "r"(dst), "l"(src));
}
__device__ __forceinline__ uint32_t pack_f16(float lo, float hi) {
    const __half2 h = __floats2half2_rn(lo, hi);
    return *reinterpret_cast<const uint32_t*>(&h);
}
// exp2 of two fp32 values -> packed half2 (one f16x2 MUFU instead of two fp32)
__device__ __forceinline__ uint32_t ex2h2(float lo, float hi) {
    uint32_t h, r;
    asm("cvt.rn.f16x2.f32 %0, %1, %2;" : "=r"(h) : "f"(hi), "f"(lo));
    asm("ex2.approx.f16x2 %0, %1;" : "=r"(r) : "r"(h));
    return r;
}

// ---------------------------------------------------------------------------
// fp16 HMMA GEMM: C[M,N] = A[M,1024] @ B[N,1024]^T.   (round-11, unchanged)
// OMODE: 0 fp32 out | 1 RoPE -> fp16 | 2 RoPE+0.125*log2e -> fp16 | 3 V^T fp16
// CTA 128x128, 8 warps (warp 64x32), K-chunk 64, cp.async double buffer.
// ---------------------------------------------------------------------------
#define GSM_STAGE 32768
#define GSM_TOT   65536

template <int OMODE>
__device__ __forceinline__ void gemm_hmma(
    const __half* __restrict__ A, const __half* __restrict__ B,
    float* __restrict__ Cf, __half* __restrict__ Ch,
    int N, int brow, int bcol,
    const float* __restrict__ fc, const float* __restrict__ fs)
{
    extern __shared__ char gsm[];
    const uint32_t sb = (uint32_t)__cvta_generic_to_shared(gsm);

    const int tid  = threadIdx.x;
    const int wid  = tid >> 5;
    const int lane = tid & 31;
    const int m_base = (wid >> 2) * 64;
    const int n_base = (wid & 3) * 32;

    const int lrow = tid >> 1;                 // 128 rows, 2 thr/row
    const __half* Asrc = A + (size_t)(brow + lrow) * KDIM;
    const __half* Bsrc = B + (size_t)(bcol + lrow) * KDIM;

    float acc[4][4][4];
    #pragma unroll
    for (int mi = 0; mi < 4; ++mi)
        #pragma unroll
        for (int nj = 0; nj < 4; ++nj)
            #pragma unroll
            for (int e = 0; e < 4; ++e) acc[mi][nj][e] = 0.f;

    const int arow0 = (lane & 15);
    const int akoff = (lane >> 4);
    const int brw   = ((lane >> 4) << 3) + (lane & 7);
    const int bkoff = ((lane >> 3) & 1);

    auto load_chunk = [&](int st, int c) {
        const uint32_t stoff = sb + (uint32_t)(st * GSM_STAGE);
        #pragma unroll
        for (int j = 0; j < 4; ++j) {
            const int cc = (tid & 1) * 4 + j;
            const uint32_t sw = (uint32_t)(((cc ^ (lrow & 7)) << 4) + (lrow << 7));
            cp16(stoff +         sw, Asrc + c * 64 + cc * 8);
            cp16(stoff + 16384 + sw, Bsrc + c * 64 + cc * 8);
        }
        asm volatile("cp.async.commit_group;");
    };

    const int NCH = KDIM / 64;   // 16
    load_chunk(0, 0);

    #pragma unroll 1
    for (int c = 0; c < NCH; ++c) {
        const int cur = c & 1;
        if (c + 1 < NCH) {
            load_chunk(cur ^ 1, c + 1);
            asm volatile("cp.async.wait_group 1;");
        } else {
            asm volatile("cp.async.wait_group 0;");
        }
        __syncthreads();
        const uint32_t stoff = sb + (uint32_t)(cur * GSM_STAGE);

        #pragma unroll
        for (int kc = 0; kc < 4; ++kc) {
            uint32_t bf[4][2];
            #pragma unroll
            for (int g = 0; g < 2; ++g) {
                const int r = n_base + g * 16 + brw;
                const uint32_t ch = (uint32_t)((((2 * kc + bkoff) ^ (r & 7)) << 4) +
                                               (r << 7));
                uint32_t t4[4];
                ldsm_x4(t4, stoff + 16384 + ch);
                bf[g * 2][0] = t4[0]; bf[g * 2][1] = t4[1];
                bf[g * 2 + 1][0] = t4[2]; bf[g * 2 + 1][1] = t4[3];
            }
            uint32_t af[4][4];
            #pragma unroll
            for (int mi = 0; mi < 4; ++mi) {
                const int r = m_base + mi * 16 + arow0;
                const uint32_t ch = (uint32_t)((((2 * kc + akoff) ^ (r & 7)) << 4) +
                                               (r << 7));
                ldsm_x4(af[mi], stoff + ch);
            }
            #pragma unroll
            for (int mi = 0; mi < 4; ++mi)
                #pragma unroll
                for (int nj = 0; nj < 4; ++nj)
                    mma16816(acc[mi][nj], af[mi], bf[nj]);
        }
        __syncthreads();
    }

    const int rbase = brow + m_base + (lane >> 2);
    const int cbase = bcol + n_base + (lane & 3) * 2;
    #pragma unroll
    for (int mi = 0; mi < 4; ++mi) {
        #pragma unroll
        for (int half = 0; half < 2; ++half) {
            const int r = rbase + mi * 16 + half * 8;
            const int srow = r & (SEQ - 1);
            #pragma unroll
            for (int nj = 0; nj < 4; ++nj) {
                const int col = cbase + nj * 8;
                float v0 = acc[mi][nj][half * 2];
                float v1 = acc[mi][nj][half * 2 + 1];
                if (OMODE == 1 || OMODE == 2) {
                    const int pair = (col & 63) >> 1;
                    const float cc = fc[srow * 32 + pair];
                    const float ss = fs[srow * 32 + pair];
                    float orv = v0 * cc - v1 * ss;
                    float oiv = v0 * ss + v1 * cc;
                    if (OMODE == 2) {
                        // 0.125 * log2(e): fold 1/sqrt(d) + exp2 conversion
                        orv *= 0.1803368801111244f; oiv *= 0.1803368801111244f;
                    }
                    const __half2 hv = __floats2half2_rn(orv, oiv);
                    *reinterpret_cast<__half2*>(Ch + (size_t)r * N + col) = hv;
                } else if (OMODE == 3) {
                    // V^T: dst[(b*4+hk)*64 + d][s]
                    const int b  = r >> 11;
                    const int s  = r & (SEQ - 1);
                    const int hk = col >> 6;
                    const int d  = col & 63;
                    __half* dst = Ch + ((size_t)((b * 4 + hk) * 64 + d)) * SEQ + s;
                    dst[0]   = __float2half(v0);
                    dst[SEQ] = __float2half(v1);
                } else {
                    *reinterpret_cast<float2*>(Cf + (size_t)r * N + col) = make_float2(v0, v1);
                }
            }
        }
    }
}

// Fused QKV: bx 0-7 Q (+RoPE+scale), 8-9 K (+RoPE), 10-11 V (->V^T)
__global__ void __launch_bounds__(256, 2) qkv_hmma_kernel(
    const float* __restrict__ fc, const float* __restrict__ fs)
{
    const int bx   = blockIdx.x;
    const int brow = blockIdx.y * 128;
    if (bx < 8)
        gemm_hmma<2>(g_xh, g_wqt, nullptr, g_qh, 1024, brow, bx * 128, fc, fs);
    else if (bx < 10)
        gemm_hmma<1>(g_xh, g_wkt, nullptr, g_kh, 256, brow, (bx - 8) * 128, fc, fs);
    else
        gemm_hmma<3>(g_xh, g_wvt, nullptr, g_vth, 256, brow, (bx - 10) * 128, nullptr, nullptr);
}

__global__ void __launch_bounds__(256, 2) oproj_hmma_kernel(float* __restrict__ out)
{
    gemm_hmma<0>(g_oh, g_wot, out, nullptr, 1024,
                 blockIdx.y * 128, blockIdx.x * 128, nullptr, nullptr);
}

// ---------------------------------------------------------------------------
// Fused prep: [0,4096) x->fp16 | then wq, wk, wv, wo transpose->fp16
// ---------------------------------------------------------------------------
__device__ __forceinline__ void wconv_body(
    const float* __restrict__ W, __half* __restrict__ T, int N, int n0, int k0)
{
    __shared__ float t[32][33];
    const int tx = threadIdx.x & 31, ty = threadIdx.x >> 5;
    #pragma unroll
    for (int i = 0; i < 32; i += 8)
        t[ty + i][tx] = W[(size_t)(k0 + ty + i) * N + n0 + tx];
    __syncthreads();
    #pragma unroll
    for (int i = 0; i < 32; i += 8)
        T[(size_t)(n0 + ty + i) * 1024 + k0 + tx] = __float2half(t[tx][ty + i]);
}

__global__ void __launch_bounds__(256) prep_kernel(
    const float* __restrict__ x,
    const float* __restrict__ wq, const float* __restrict__ wk,
    const float* __restrict__ wv, const float* __restrict__ wo)
{
    const int bid = blockIdx.x;
    if (bid < 4096) {
        const int i = bid * 256 + threadIdx.x;
        const float4 v = reinterpret_cast<const float4*>(x)[i];
        uint2 st;
        st.x = pack_f16(v.x, v.y);
        st.y = pack_f16(v.z, v.w);
        reinterpret_cast<uint2*>(g_xh)[i] = st;
    } else if (bid < 5120) {
        const int i = bid - 4096;
        wconv_body(wq, g_wqt, 1024, (i & 31) * 32, (i >> 5) * 32);
    } else if (bid < 5376) {
        const int i = bid - 5120;
        wconv_body(wk, g_wkt, 256, (i & 7) * 32, (i >> 3) * 32);
    } else if (bid < 5632) {
        const int i = bid - 5376;
        wconv_body(wv, g_wvt, 256, (i & 7) * 32, (i >> 3) * 32);
    } else {
        const int i = bid - 5632;
        wconv_body(wo, g_wot, 1024, (i & 31) * 32, (i >> 5) * 32);
    }
}

// ---------------------------------------------------------------------------
// Tensor-core flash attention (fp16, exp2 domain, f16x2 MUFU softmax).
// CTA = 128 queries x (b,h). 8 warps x 16 query rows (256 threads).
// K-tiles of 64 keys, double-buffered cp.async.
// l computed via ones-vector HMMA (exact row sums, no shfl reduction).
// smem: Q 16K | stage{0,1}: K 8K + V^T 8K   (48 KB dynamic)
// ---------------------------------------------------------------------------
#define ASM_Q   0
#define ASM_ST  16384
#define ASM_TOT 49152

__global__ void __launch_bounds__(256, 2) attn_mma_kernel()
{
    extern __shared__ char asmem[];
    const uint32_t sb = (uint32_t)__cvta_generic_to_shared(asmem);
    const int tid = threadIdx.x, w = tid >> 5, lane = tid & 31;
    const int b = blockIdx.z, h = blockIdx.y;
    const int qt = (int)gridDim.x - 1 - blockIdx.x;   // heavy tiles first
    const int hk = h >> 2;
    const int q0 = qt * 128;
    const int ntiles = 2 * qt + 2;

    // --- Q tile load (once): 128 rows x 64 d ---
    {
        const int row = tid >> 1;
        const size_t qoff = (size_t)(b * SEQ + q0 + row) * 1024 + h * 64;
        #pragma unroll
        for (int j = 0; j < 4; ++j) {
            const int c = (tid & 1) * 4 + j;
            const uint32_t sw = (uint32_t)((c ^ (row & 7)) << 4) + (uint32_t)(row << 7);
            cp16(sb + ASM_Q + sw, g_qh + qoff + c * 8);
        }
        asm volatile("cp.async.commit_group;");
    }
    auto load_stage = [&](int st, int kt) {
        const int row = tid >> 2;                    // 64 rows
        const uint32_t so = sb + ASM_ST + (uint32_t)st * 16384;
        const size_t koff = (size_t)(b * SEQ + kt * 64 + row) * 256 + hk * 64;
        const size_t voff = (size_t)((b * 4 + hk) * 64 + row) * SEQ + kt * 64;
        #pragma unroll
        for (int i = 0; i < 2; ++i) {
            const int c = (tid & 3) * 2 + i;
            const uint32_t sw = (uint32_t)((c ^ (row & 7)) << 4) + (uint32_t)(row << 7);
            cp16(so +        sw, g_kh + koff + c * 8);
            cp16(so + 8192 + sw, g_vth + voff + c * 8);
        }
        asm volatile("cp.async.commit_group;");
    };
    load_stage(0, 0);

    const int arow = lane & 15, akoff = lane >> 4;
    const int brw  = ((lane >> 4) << 3) + (lane & 7);
    const int bkoff = (lane >> 3) & 1;

    // --- hoist Q fragments (warp owns rows w*16 .. w*16+15) ---
    asm volatile("cp.async.wait_group 1;");
    __syncthreads();
    uint32_t qf[4][4];
    #pragma unroll
    for (int kc = 0; kc < 4; ++kc) {
        const int r = w * 16 + arow;
        const uint32_t ch = (uint32_t)(((2 * kc + akoff) ^ (r & 7)) << 4) +
                            (uint32_t)(r << 7);
        ldsm_x4(qf[kc], sb + ASM_Q + ch);
    }

    float o[8][4];
    #pragma unroll
    for (int nj = 0; nj < 8; ++nj)
        #pragma unroll
        for (int e = 0; e < 4; ++e) o[nj][e] = 0.f;
    float lacc[4] = {0.f, 0.f, 0.f, 0.f};           // row-sum accum via ones-MMA
    float mrow[2] = {-1e30f, -1e30f};
    const uint32_t ones2[2] = {0x3C003C00u, 0x3C003C00u};  // f16 1.0 x4

    #pragma unroll 1
    for (int kt = 0; kt < ntiles; ++kt) {
        const int st = kt & 1;
        if (kt + 1 < ntiles) {
            load_stage(st ^ 1, kt + 1);
            asm volatile("cp.async.wait_group 1;");
        } else {
            asm volatile("cp.async.wait_group 0;");
        }
        __syncthreads();
        const uint32_t so = sb + ASM_ST + (uint32_t)st * 16384;

        // ---- S = Q @ K^T (scores already in log2 domain) ----
        float sc[8][4];
        #pragma unroll
        for (int nj = 0; nj < 8; ++nj)
            #pragma unroll
            for (int e = 0; e < 4; ++e) sc[nj][e] = 0.f;

        #pragma unroll
        for (int kc = 0; kc < 4; ++kc) {
            uint32_t kb[8][2];
            #pragma unroll
            for (int g = 0; g < 4; ++g) {
                const int r = g * 16 + brw;
                const uint32_t ch = (uint32_t)(((2 * kc + bkoff) ^ (r & 7)) << 4) +
                                    (uint32_t)(r << 7);
                uint32_t t4[4];
                ldsm_x4(t4, so + ch);
                kb[g * 2][0] = t4[0]; kb[g * 2][1] = t4[1];
                kb[g * 2 + 1][0] = t4[2]; kb[g * 2 + 1][1] = t4[3];
            }
            #pragma unroll
            for (int nj = 0; nj < 8; ++nj)
                mma16816(sc[nj], qf[kc], kb[nj]);
        }

        // ---- causal mask (partial tiles only) ----
        const int qwbase = q0 + w * 16;
        if (kt * 64 + 63 > qwbase) {
            const int jb = kt * 64 + (lane & 3) * 2;
            const int qb = qwbase + (lane >> 2);
            #pragma unroll
            for (int nj = 0; nj < 8; ++nj)
                #pragma unroll
                for (int e = 0; e < 4; ++e) {
                    const int j = jb + nj * 8 + (e & 1);
                    const int q = qb + ((e >> 1) << 3);
                    if (j > q) sc[nj][e] = -1e30f;
                }
        }

        // ---- online softmax (base-2) max/rescale ----
        float tm[2] = {-1e30f, -1e30f};
        #pragma unroll
        for (int nj = 0; nj < 8; ++nj)
            #pragma unroll
            for (int e = 0; e < 4; ++e)
                tm[e >> 1] = fmaxf(tm[e >> 1], sc[nj][e]);
        float alpha[2];
        #pragma unroll
        for (int ri = 0; ri < 2; ++ri) {
            tm[ri] = fmaxf(tm[ri], __shfl_xor_sync(0xffffffffu, tm[ri], 1));
            tm[ri] = fmaxf(tm[ri], __shfl_xor_sync(0xffffffffu, tm[ri], 2));
            const float nm = fmaxf(mrow[ri], tm[ri]);
            alpha[ri] = exp2f(mrow[ri] - nm);
            mrow[ri] = nm;
        }
        const bool chg = (alpha[0] < 1.f) || (alpha[1] < 1.f);
        if (__any_sync(0xffffffffu, chg)) {
            #pragma unroll
            for (int nj = 0; nj < 8; ++nj) {
                o[nj][0] *= alpha[0]; o[nj][1] *= alpha[0];
                o[nj][2] *= alpha[1]; o[nj][3] *= alpha[1];
            }
            lacc[0] *= alpha[0]; lacc[1] *= alpha[0];
            lacc[2] *= alpha[1]; lacc[3] *= alpha[1];
        }

        // ---- p = exp2(s-m) as packed half2 (f16x2 MUFU); l += P @ ones ----
        uint32_t ap[4][4];
        #pragma unroll
        for (int kc = 0; kc < 4; ++kc) {
            const float* s0 = sc[2 * kc];
            const float* s1 = sc[2 * kc + 1];
            ap[kc][0] = ex2h2(s0[0] - mrow[0], s0[1] - mrow[0]);
            ap[kc][1] = ex2h2(s0[2] - mrow[1], s0[3] - mrow[1]);
            ap[kc][2] = ex2h2(s1[0] - mrow[0], s1[1] - mrow[0]);
            ap[kc][3] = ex2h2(s1[2] - mrow[1], s1[3] - mrow[1]);
            mma16816(lacc, ap[kc], ones2);
        }

        // ---- O += P @ V ----
        #pragma unroll
        for (int kc = 0; kc < 4; ++kc) {
            uint32_t vb[8][2];
            #pragma unroll
            for (int g = 0; g < 4; ++g) {
                const int r = g * 16 + brw;
                const uint32_t ch = (uint32_t)(((2 * kc + bkoff) ^ (r & 7)) << 4) +
                                    (uint32_t)(r << 7);
                uint32_t t4[4];
                ldsm_x4(t4, so + 8192 + ch);
                vb[g * 2][0] = t4[0]; vb[g * 2][1] = t4[1];
                vb[g * 2 + 1][0] = t4[2]; vb[g * 2 + 1][1] = t4[3];
            }
            #pragma unroll
            for (int nj = 0; nj < 8; ++nj)
                mma16816(o[nj], ap[kc], vb[nj]);
        }
        __syncthreads();
    }

    // ---- epilogue: normalize + write fp16 (lacc holds exact row sums) ----
    const float linv[2] = {1.0f / lacc[0], 1.0f / lacc[2]};
    #pragma unroll
    for (int half = 0; half < 2; ++half) {
        const int rloc = w * 16 + (lane >> 2) + half * 8;
        const size_t rg = (size_t)(b * SEQ + q0 + rloc) * 1024 + h * 64;
        const float inv = linv[half];
        #pragma unroll
        for (int nj = 0; nj < 8; ++nj) {
            const int col = nj * 8 + (lane & 3) * 2;
            const __half2 hv = __floats2half2_rn(o[nj][half * 2] * inv,
                                                 o[nj][half * 2 + 1] * inv);
            *reinterpret_cast<__half2*>(g_oh + rg + col) = hv;
        }
    }
}

// ---------------------------------------------------------------------------
// Inputs: x, start_pos, freqs_cos, freqs_sin, mask, wq, wk, wv, wo
// ---------------------------------------------------------------------------
extern "C" void kernel_launch(void* const* d_in, const int* in_sizes, int n_in,
                              void* d_out, int out_size)
{
    const float* x  = (const float*)d_in[0];
    const float* fc = (const float*)d_in[2];
    const float* fs = (const float*)d_in[3];
    const float* wq = (const float*)d_in[5];
    const float* wk = (const float*)d_in[6];
    const float* wv = (const float*)d_in[7];
    const float* wo = (const float*)d_in[8];
    float* out = (float*)d_out;

    cudaFuncSetAttribute(qkv_hmma_kernel,
                         cudaFuncAttributeMaxDynamicSharedMemorySize, GSM_TOT);
    cudaFuncSetAttribute(oproj_hmma_kernel,
                         cudaFuncAttributeMaxDynamicSharedMemorySize, GSM_TOT);
    cudaFuncSetAttribute(attn_mma_kernel,
                         cudaFuncAttributeMaxDynamicSharedMemorySize, ASM_TOT);

    // Fused prep: x -> fp16; weights -> transposed fp16
    prep_kernel<<<6656, 256>>>(x, wq, wk, wv, wo);
    // QKV projection (fp16 HMMA; Q/K RoPE'd fp16; V written transposed)
    qkv_hmma_kernel<<<dim3(12, 32), 256, GSM_TOT>>>(fc, fs);
    // Tensor-core flash attention (256 thr, 8 warps x 16 rows)
    attn_mma_kernel<<<dim3(16, 16, 2), 256, ASM_TOT>>>();
    // Output projection -> d_out (fp32)
    oproj_hmma_kernel<<<dim3(8, 32), 256, GSM_TOT>>>(out);
}

// round 13
// speedup vs baseline: 1.5839x; 1.0125x over previous
#include <cuda_runtime.h>
#include <cuda_fp16.h>
#include <cstddef>
#include <cstdint>

#define SEQ    2048
#define KDIM   1024

// ---------------------------------------------------------------------------
// Device scratch (no allocation allowed)
// ---------------------------------------------------------------------------
__device__ __half g_xh[4096 * 1024];                 // x fp16
__device__ __half g_wqt[1024 * 1024];                // W^T [N,K] fp16
__device__ __half g_wkt[256 * 1024];
__device__ __half g_wvt[256 * 1024];
__device__ __half g_wot[1024 * 1024];
__device__ __half g_qh[4096 * 1024];                 // Q RoPE'd, ×0.125·log2e
__device__ __half g_kh[4096 * 256];                  // K RoPE'd
__device__ __half g_vth[8 * 64 * 2048];              // V^T [(b*4+hk)][d][s]
__device__ __half g_oh[4096 * 1024];                 // attention out

// ---------------------------------------------------------------------------
// PTX helpers (architecture-generic; plain sm_103 target)
// ---------------------------------------------------------------------------
__device__ __forceinline__ void ldsm_x4(uint32_t r[4], uint32_t addr) {
    asm volatile("ldmatrix.sync.aligned.m8n8.x4.shared.b16 {%0,%1,%2,%3}, [%4];"
        : "=r"(r[0]), "=r"(r[1]), "=r"(r[2]), "=r"(r[3]) : "r"(addr));
}
__device__ __forceinline__ void mma16816(float c[4], const uint32_t a[4], const uint32_t b[2]) {
    asm volatile(
        "mma.sync.aligned.m16n8k16.row.col.f32.f16.f16.f32 "
        "{%0,%1,%2,%3}, {%4,%5,%6,%7}, {%8,%9}, {%0,%1,%2,%3};"
        : "+f"(c[0]), "+f"(c[1]), "+f"(c[2]), "+f"(c[3])
        : "r"(a[0]), "r"(a[1]), "r"(a[2]), "r"(a[3]), "r"(b[0]), "r"(b[1]));
}
__device__ __forceinline__ void cp16(uint32_t dst, const void* src) {
    asm volatile("cp.async.cg.shared.global [%0], [%1], 16;" :: "r"(dst), "l"(src));
}
__device__ __forceinline__ uint32_t pack_f16(float lo, float hi) {
    const __half2 h = __floats2half2_rn(lo, hi);
    return *reinterpret_cast<const uint32_t*>(&h);
}
// exp2 of two fp32 values -> packed half2 (one f16x2 MUFU instead of two fp32)
__device__ __forceinline__ uint32_t ex2h2(float lo, float hi) {
    uint32_t h, r;
    asm("cvt.rn.f16x2.f32 %0, %1, %2;" : "=r"(h) : "f"(hi), "f"(lo));
    asm("ex2.approx.f16x2 %0, %1;" : "=r"(r) : "r"(h));
    return r;
}

// ---------------------------------------------------------------------------
// fp16 HMMA GEMM: C[M,N] = A[M,1024] @ B[N,1024]^T.
// OMODE: 0 fp32 out | 1 RoPE -> fp16 | 2 RoPE+0.125*log2e -> fp16 | 3 V^T fp16
// CTA 128x128, SIXTEEN warps (512 thr, warp 32x32, 4x4 grid), K-chunk 64,
// cp.async double buffer (known-good structure). acc=32 regs -> ~64 regs/thr
// -> 2 CTA/SM = 32 warps/SM (50% occ) for latency hiding.
// smem: 2 stages x (A 16K + B 16K) = 64 KB dynamic.
// ---------------------------------------------------------------------------
#define GSM_STAGE 32768
#define GSM_TOT   65536

template <int OMODE>
__device__ __forceinline__ void gemm_hmma(
    const __half* __restrict__ A, const __half* __restrict__ B,
    float* __restrict__ Cf, __half* __restrict__ Ch,
    int N, int brow, int bcol,
    const float* __restrict__ fc, const float* __restrict__ fs)
{
    extern __shared__ char gsm[];
    const uint32_t sb = (uint32_t)__cvta_generic_to_shared(gsm);

    const int tid  = threadIdx.x;
    const int wid  = tid >> 5;
    const int lane = tid & 31;
    const int m_base = (wid >> 2) * 32;   // 4 warp rows
    const int n_base = (wid & 3) * 32;    // 4 warp cols

    const int lrow = tid >> 2;                 // 128 rows, 4 thr/row
    const __half* Asrc = A + (size_t)(brow + lrow) * KDIM;
    const __half* Bsrc = B + (size_t)(bcol + lrow) * KDIM;

    float acc[2][4][4];
    #pragma unroll
    for (int mi = 0; mi < 2; ++mi)
        #pragma unroll
        for (int nj = 0; nj < 4; ++nj)
            #pragma unroll
            for (int e = 0; e < 4; ++e) acc[mi][nj][e] = 0.f;

    const int arow0 = (lane & 15);
    const int akoff = (lane >> 4);
    const int brw   = ((lane >> 4) << 3) + (lane & 7);
    const int bkoff = ((lane >> 3) & 1);

    auto load_chunk = [&](int st, int c) {
        const uint32_t stoff = sb + (uint32_t)(st * GSM_STAGE);
        #pragma unroll
        for (int j = 0; j < 2; ++j) {
            const int cc = (tid & 3) * 2 + j;
            const uint32_t sw = (uint32_t)(((cc ^ (lrow & 7)) << 4) + (lrow << 7));
            cp16(stoff +         sw, Asrc + c * 64 + cc * 8);
            cp16(stoff + 16384 + sw, Bsrc + c * 64 + cc * 8);
        }
        asm volatile("cp.async.commit_group;");
    };

    const int NCH = KDIM / 64;   // 16
    load_chunk(0, 0);

    #pragma unroll 1
    for (int c = 0; c < NCH; ++c) {
        const int cur = c & 1;
        if (c + 1 < NCH) {
            load_chunk(cur ^ 1, c + 1);
            asm volatile("cp.async.wait_group 1;");
        } else {
            asm volatile("cp.async.wait_group 0;");
        }
        __syncthreads();
        const uint32_t stoff = sb + (uint32_t)(cur * GSM_STAGE);

        #pragma unroll
        for (int kc = 0; kc < 4; ++kc) {
            uint32_t bf[4][2];
            #pragma unroll
            for (int g = 0; g < 2; ++g) {
                const int r = n_base + g * 16 + brw;
                const uint32_t ch = (uint32_t)((((2 * kc + bkoff) ^ (r & 7)) << 4) +
                                               (r << 7));
                uint32_t t4[4];
                ldsm_x4(t4, stoff + 16384 + ch);
                bf[g * 2][0] = t4[0]; bf[g * 2][1] = t4[1];
                bf[g * 2 + 1][0] = t4[2]; bf[g * 2 + 1][1] = t4[3];
            }
            #pragma unroll
            for (int mi = 0; mi < 2; ++mi) {
                const int r = m_base + mi * 16 + arow0;
                const uint32_t ch = (uint32_t)((((2 * kc + akoff) ^ (r & 7)) << 4) +
                                               (r << 7));
                uint32_t af[4];
                ldsm_x4(af, stoff + ch);
                #pragma unroll
                for (int nj = 0; nj < 4; ++nj)
                    mma16816(acc[mi][nj], af, bf[nj]);
            }
        }
        __syncthreads();
    }

    const int rbase = brow + m_base + (lane >> 2);
    const int cbase = bcol + n_base + (lane & 3) * 2;
    #pragma unroll
    for (int mi = 0; mi < 2; ++mi) {
        #pragma unroll
        for (int half = 0; half < 2; ++half) {
            const int r = rbase + mi * 16 + half * 8;
            const int srow = r & (SEQ - 1);
            #pragma unroll
            for (int nj = 0; nj < 4; ++nj) {
                const int col = cbase + nj * 8;
                float v0 = acc[mi][nj][half * 2];
                float v1 = acc[mi][nj][half * 2 + 1];
                if (OMODE == 1 || OMODE == 2) {
                    const int pair = (col & 63) >> 1;
                    const float cc = fc[srow * 32 + pair];
                    const float ss = fs[srow * 32 + pair];
                    float orv = v0 * cc - v1 * ss;
                    float oiv = v0 * ss + v1 * cc;
                    if (OMODE == 2) {
                        // 0.125 * log2(e): fold 1/sqrt(d) + exp2 conversion
                        orv *= 0.1803368801111244f; oiv *= 0.1803368801111244f;
                    }
                    const __half2 hv = __floats2half2_rn(orv, oiv);
                    *reinterpret_cast<__half2*>(Ch + (size_t)r * N + col) = hv;
                } else if (OMODE == 3) {
                    // V^T: dst[(b*4+hk)*64 + d][s]
                    const int b  = r >> 11;
                    const int s  = r & (SEQ - 1);
                    const int hk = col >> 6;
                    const int d  = col & 63;
                    __half* dst = Ch + ((size_t)((b * 4 + hk) * 64 + d)) * SEQ + s;
                    dst[0]   = __float2half(v0);
                    dst[SEQ] = __float2half(v1);
                } else {
                    *reinterpret_cast<float2*>(Cf + (size_t)r * N + col) = make_float2(v0, v1);
                }
            }
        }
    }
}

// Fused QKV: bx 0-7 Q (+RoPE+scale), 8-9 K (+RoPE), 10-11 V (->V^T)
__global__ void __launch_bounds__(512, 2) qkv_hmma_kernel(
    const float* __restrict__ fc, const float* __restrict__ fs)
{
    const int bx   = blockIdx.x;
    const int brow = blockIdx.y * 128;
    if (bx < 8)
        gemm_hmma<2>(g_xh, g_wqt, nullptr, g_qh, 1024, brow, bx * 128, fc, fs);
    else if (bx < 10)
        gemm_hmma<1>(g_xh, g_wkt, nullptr, g_kh, 256, brow, (bx - 8) * 128, fc, fs);
    else
        gemm_hmma<3>(g_xh, g_wvt, nullptr, g_vth, 256, brow, (bx - 10) * 128, nullptr, nullptr);
}

__global__ void __launch_bounds__(512, 2) oproj_hmma_kernel(float* __restrict__ out)
{
    gemm_hmma<0>(g_oh, g_wot, out, nullptr, 1024,
                 blockIdx.y * 128, blockIdx.x * 128, nullptr, nullptr);
}

// ---------------------------------------------------------------------------
// Fused prep: [0,4096) x->fp16 | then wq, wk, wv, wo transpose->fp16
// ---------------------------------------------------------------------------
__device__ __forceinline__ void wconv_body(
    const float* __restrict__ W, __half* __restrict__ T, int N, int n0, int k0)
{
    __shared__ float t[32][33];
    const int tx = threadIdx.x & 31, ty = threadIdx.x >> 5;
    #pragma unroll
    for (int i = 0; i < 32; i += 8)
        t[ty + i][tx] = W[(size_t)(k0 + ty + i) * N + n0 + tx];
    __syncthreads();
    #pragma unroll
    for (int i = 0; i < 32; i += 8)
        T[(size_t)(n0 + ty + i) * 1024 + k0 + tx] = __float2half(t[tx][ty + i]);
}

__global__ void __launch_bounds__(256) prep_kernel(
    const float* __restrict__ x,
    const float* __restrict__ wq, const float* __restrict__ wk,
    const float* __restrict__ wv, const float* __restrict__ wo)
{
    const int bid = blockIdx.x;
    if (bid < 4096) {
        const int i = bid * 256 + threadIdx.x;
        const float4 v = reinterpret_cast<const float4*>(x)[i];
        uint2 st;
        st.x = pack_f16(v.x, v.y);
        st.y = pack_f16(v.z, v.w);
        reinterpret_cast<uint2*>(g_xh)[i] = st;
    } else if (bid < 5120) {
        const int i = bid - 4096;
        wconv_body(wq, g_wqt, 1024, (i & 31) * 32, (i >> 5) * 32);
    } else if (bid < 5376) {
        const int i = bid - 5120;
        wconv_body(wk, g_wkt, 256, (i & 7) * 32, (i >> 3) * 32);
    } else if (bid < 5632) {
        const int i = bid - 5376;
        wconv_body(wv, g_wvt, 256, (i & 7) * 32, (i >> 3) * 32);
    } else {
        const int i = bid - 5632;
        wconv_body(wo, g_wot, 1024, (i & 31) * 32, (i >> 5) * 32);
    }
}

// ---------------------------------------------------------------------------
// Tensor-core flash attention (fp16, exp2 domain, f16x2 MUFU softmax).
// (round-12, byte-identical)
// CTA = 128 queries x (b,h). 8 warps x 16 query rows (256 threads).
// K-tiles of 64 keys, double-buffered cp.async.
// l computed via ones-vector HMMA (exact row sums, no shfl reduction).
// smem: Q 16K | stage{0,1}: K 8K + V^T 8K   (48 KB dynamic)
// ---------------------------------------------------------------------------
#define ASM_Q   0
#define ASM_ST  16384
#define ASM_TOT 49152

__global__ void __launch_bounds__(256, 2) attn_mma_kernel()
{
    extern __shared__ char asmem[];
    const uint32_t sb = (uint32_t)__cvta_generic_to_shared(asmem);
    const int tid = threadIdx.x, w = tid >> 5, lane = tid & 31;
    const int b = blockIdx.z, h = blockIdx.y;
    const int qt = (int)gridDim.x - 1 - blockIdx.x;   // heavy tiles first
    const int hk = h >> 2;
    const int q0 = qt * 128;
    const int ntiles = 2 * qt + 2;

    // --- Q tile load (once): 128 rows x 64 d ---
    {
        const int row = tid >> 1;
        const size_t qoff = (size_t)(b * SEQ + q0 + row) * 1024 + h * 64;
        #pragma unroll
        for (int j = 0; j < 4; ++j) {
            const int c = (tid & 1) * 4 + j;
            const uint32_t sw = (uint32_t)((c ^ (row & 7)) << 4) + (uint32_t)(row << 7);
            cp16(sb + ASM_Q + sw, g_qh + qoff + c * 8);
        }
        asm volatile("cp.async.commit_group;");
    }
    auto load_stage = [&](int st, int kt) {
        const int row = tid >> 2;                    // 64 rows
        const uint32_t so = sb + ASM_ST + (uint32_t)st * 16384;
        const size_t koff = (size_t)(b * SEQ + kt * 64 + row) * 256 + hk * 64;
        const size_t voff = (size_t)((b * 4 + hk) * 64 + row) * SEQ + kt * 64;
        #pragma unroll
        for (int i = 0; i < 2; ++i) {
            const int c = (tid & 3) * 2 + i;
            const uint32_t sw = (uint32_t)((c ^ (row & 7)) << 4) + (uint32_t)(row << 7);
            cp16(so +        sw, g_kh + koff + c * 8);
            cp16(so + 8192 + sw, g_vth + voff + c * 8);
        }
        asm volatile("cp.async.commit_group;");
    };
    load_stage(0, 0);

    const int arow = lane & 15, akoff = lane >> 4;
    const int brw  = ((lane >> 4) << 3) + (lane & 7);
    const int bkoff = (lane >> 3) & 1;

    // --- hoist Q fragments (warp owns rows w*16 .. w*16+15) ---
    asm volatile("cp.async.wait_group 1;");
    __syncthreads();
    uint32_t qf[4][4];
    #pragma unroll
    for (int kc = 0; kc < 4; ++kc) {
        const int r = w * 16 + arow;
        const uint32_t ch = (uint32_t)(((2 * kc + akoff) ^ (r & 7)) << 4) +
                            (uint32_t)(r << 7);
        ldsm_x4(qf[kc], sb + ASM_Q + ch);
    }

    float o[8][4];
    #pragma unroll
    for (int nj = 0; nj < 8; ++nj)
        #pragma unroll
        for (int e = 0; e < 4; ++e) o[nj][e] = 0.f;
    float lacc[4] = {0.f, 0.f, 0.f, 0.f};           // row-sum accum via ones-MMA
    float mrow[2] = {-1e30f, -1e30f};
    const uint32_t ones2[2] = {0x3C003C00u, 0x3C003C00u};  // f16 1.0 x4

    #pragma unroll 1
    for (int kt = 0; kt < ntiles; ++kt) {
        const int st = kt & 1;
        if (kt + 1 < ntiles) {
            load_stage(st ^ 1, kt + 1);
            asm volatile("cp.async.wait_group 1;");
        } else {
            asm volatile("cp.async.wait_group 0;");
        }
        __syncthreads();
        const uint32_t so = sb + ASM_ST + (uint32_t)st * 16384;

        // ---- S = Q @ K^T (scores already in log2 domain) ----
        float sc[8][4];
        #pragma unroll
        for (int nj = 0; nj < 8; ++nj)
            #pragma unroll
            for (int e = 0; e < 4; ++e) sc[nj][e] = 0.f;

        #pragma unroll
        for (int kc = 0; kc < 4; ++kc) {
            uint32_t kb[8][2];
            #pragma unroll
            for (int g = 0; g < 4; ++g) {
                const int r = g * 16 + brw;
                const uint32_t ch = (uint32_t)(((2 * kc + bkoff) ^ (r & 7)) << 4) +
                                    (uint32_t)(r << 7);
                uint32_t t4[4];
                ldsm_x4(t4, so + ch);
                kb[g * 2][0] = t4[0]; kb[g * 2][1] = t4[1];
                kb[g * 2 + 1][0] = t4[2]; kb[g * 2 + 1][1] = t4[3];
            }
            #pragma unroll
            for (int nj = 0; nj < 8; ++nj)
                mma16816(sc[nj], qf[kc], kb[nj]);
        }

        // ---- causal mask (partial tiles only) ----
        const int qwbase = q0 + w * 16;
        if (kt * 64 + 63 > qwbase) {
            const int jb = kt * 64 + (lane & 3) * 2;
            const int qb = qwbase + (lane >> 2);
            #pragma unroll
            for (int nj = 0; nj < 8; ++nj)
                #pragma unroll
                for (int e = 0; e < 4; ++e) {
                    const int j = jb + nj * 8 + (e & 1);
                    const int q = qb + ((e >> 1) << 3);
                    if (j > q) sc[nj][e] = -1e30f;
                }
        }

        // ---- online softmax (base-2) max/rescale ----
        float tm[2] = {-1e30f, -1e30f};
        #pragma unroll
        for (int nj = 0; nj < 8; ++nj)
            #pragma unroll
            for (int e = 0; e < 4; ++e)
                tm[e >> 1] = fmaxf(tm[e >> 1], sc[nj][e]);
        float alpha[2];
        #pragma unroll
        for (int ri = 0; ri < 2; ++ri) {
            tm[ri] = fmaxf(tm[ri], __shfl_xor_sync(0xffffffffu, tm[ri], 1));
            tm[ri] = fmaxf(tm[ri], __shfl_xor_sync(0xffffffffu, tm[ri], 2));
            const float nm = fmaxf(mrow[ri], tm[ri]);
            alpha[ri] = exp2f(mrow[ri] - nm);
            mrow[ri] = nm;
        }
        const bool chg = (alpha[0] < 1.f) || (alpha[1] < 1.f);
        if (__any_sync(0xffffffffu, chg)) {
            #pragma unroll
            for (int nj = 0; nj < 8; ++nj) {
                o[nj][0] *= alpha[0]; o[nj][1] *= alpha[0];
                o[nj][2] *= alpha[1]; o[nj][3] *= alpha[1];
            }
            lacc[0] *= alpha[0]; lacc[1] *= alpha[0];
            lacc[2] *= alpha[1]; lacc[3] *= alpha[1];
        }

        // ---- p = exp2(s-m) as packed half2 (f16x2 MUFU); l += P @ ones ----
        uint32_t ap[4][4];
        #pragma unroll
        for (int kc = 0; kc < 4; ++kc) {
            const float* s0 = sc[2 * kc];
            const float* s1 = sc[2 * kc + 1];
            ap[kc][0] = ex2h2(s0[0] - mrow[0], s0[1] - mrow[0]);
            ap[kc][1] = ex2h2(s0[2] - mrow[1], s0[3] - mrow[1]);
            ap[kc][2] = ex2h2(s1[0] - mrow[0], s1[1] - mrow[0]);
            ap[kc][3] = ex2h2(s1[2] - mrow[1], s1[3] - mrow[1]);
            mma16816(lacc, ap[kc], ones2);
        }

        // ---- O += P @ V ----
        #pragma unroll
        for (int kc = 0; kc < 4; ++kc) {
            uint32_t vb[8][2];
            #pragma unroll
            for (int g = 0; g < 4; ++g) {
                const int r = g * 16 + brw;
                const uint32_t ch = (uint32_t)(((2 * kc + bkoff) ^ (r & 7)) << 4) +
                                    (uint32_t)(r << 7);
                uint32_t t4[4];
                ldsm_x4(t4, so + 8192 + ch);
                vb[g * 2][0] = t4[0]; vb[g * 2][1] = t4[1];
                vb[g * 2 + 1][0] = t4[2]; vb[g * 2 + 1][1] = t4[3];
            }
            #pragma unroll
            for (int nj = 0; nj < 8; ++nj)
                mma16816(o[nj], ap[kc], vb[nj]);
        }
        __syncthreads();
    }

    // ---- epilogue: normalize + write fp16 (lacc holds exact row sums) ----
    const float linv[2] = {1.0f / lacc[0], 1.0f / lacc[2]};
    #pragma unroll
    for (int half = 0; half < 2; ++half) {
        const int rloc = w * 16 + (lane >> 2) + half * 8;
        const size_t rg = (size_t)(b * SEQ + q0 + rloc) * 1024 + h * 64;
        const float inv = linv[half];
        #pragma unroll
        for (int nj = 0; nj < 8; ++nj) {
            const int col = nj * 8 + (lane & 3) * 2;
            const __half2 hv = __floats2half2_rn(o[nj][half * 2] * inv,
                                                 o[nj][half * 2 + 1] * inv);
            *reinterpret_cast<__half2*>(g_oh + rg + col) = hv;
        }
    }
}

// ---------------------------------------------------------------------------
// Inputs: x, start_pos, freqs_cos, freqs_sin, mask, wq, wk, wv, wo
// ---------------------------------------------------------------------------
extern "C" void kernel_launch(void* const* d_in, const int* in_sizes, int n_in,
                              void* d_out, int out_size)
{
    const float* x  = (const float*)d_in[0];
    const float* fc = (const float*)d_in[2];
    const float* fs = (const float*)d_in[3];
    const float* wq = (const float*)d_in[5];
    const float* wk = (const float*)d_in[6];
    const float* wv = (const float*)d_in[7];
    const float* wo = (const float*)d_in[8];
    float* out = (float*)d_out;

    cudaFuncSetAttribute(qkv_hmma_kernel,
                         cudaFuncAttributeMaxDynamicSharedMemorySize, GSM_TOT);
    cudaFuncSetAttribute(oproj_hmma_kernel,
                         cudaFuncAttributeMaxDynamicSharedMemorySize, GSM_TOT);
    cudaFuncSetAttribute(attn_mma_kernel,
                         cudaFuncAttributeMaxDynamicSharedMemorySize, ASM_TOT);

    // Fused prep: x -> fp16; weights -> transposed fp16
    prep_kernel<<<6656, 256>>>(x, wq, wk, wv, wo);
    // QKV projection (fp16 HMMA, 512 thr; Q/K RoPE'd fp16; V written transposed)
    qkv_hmma_kernel<<<dim3(12, 32), 512, GSM_TOT>>>(fc, fs);
    // Tensor-core flash attention (256 thr, 8 warps x 16 rows)
    attn_mma_kernel<<<dim3(16, 16, 2), 256, ASM_TOT>>>();
    // Output projection -> d_out (fp32)
    oproj_hmma_kernel<<<dim3(8, 32), 512, GSM_TOT>>>(out);
}

// round 14
// speedup vs baseline: 1.6122x; 1.0179x over previous
#include <cuda_runtime.h>
#include <cuda_fp16.h>
#include <cstddef>
#include <cstdint>

#define SEQ    2048
#define KDIM   1024

// ---------------------------------------------------------------------------
// Device scratch (no allocation allowed)
// ---------------------------------------------------------------------------
__device__ __half g_xh[4096 * 1024];                 // x fp16
__device__ __half g_wqt[1024 * 1024];                // W^T [N,K] fp16
__device__ __half g_wkt[256 * 1024];
__device__ __half g_wvt[256 * 1024];
__device__ __half g_wot[1024 * 1024];
__device__ __half g_qh[4096 * 1024];                 // Q RoPE'd, ×0.125·log2e
__device__ __half g_kh[4096 * 256];                  // K RoPE'd
__device__ __half g_vth[8 * 64 * 2048];              // V^T [(b*4+hk)][d][s]
__device__ __half g_oh[4096 * 1024];                 // attention out

// ---------------------------------------------------------------------------
// PTX helpers (architecture-generic; plain sm_103 target)
// ---------------------------------------------------------------------------
__device__ __forceinline__ void ldsm_x4(uint32_t r[4], uint32_t addr) {
    asm volatile("ldmatrix.sync.aligned.m8n8.x4.shared.b16 {%0,%1,%2,%3}, [%4];"
        : "=r"(r[0]), "=r"(r[1]), "=r"(r[2]), "=r"(r[3]) : "r"(addr));
}
__device__ __forceinline__ void mma16816(float c[4], const uint32_t a[4], const uint32_t b[2]) {
    asm volatile(
        "mma.sync.aligned.m16n8k16.row.col.f32.f16.f16.f32 "
        "{%0,%1,%2,%3}, {%4,%5,%6,%7}, {%8,%9}, {%0,%1,%2,%3};"
        : "+f"(c[0]), "+f"(c[1]), "+f"(c[2]), "+f"(c[3])
        : "r"(a[0]), "r"(a[1]), "r"(a[2]), "r"(a[3]), "r"(b[0]), "r"(b[1]));
}
__device__ __forceinline__ void cp16(uint32_t dst, const void* src) {
    asm volatile("cp.async.cg.shared.global [%0], [%1], 16;" :: "r"(dst), "l"(src));
}
__device__ __forceinline__ uint32_t pack_f16(float lo, float hi) {
    const __half2 h = __floats2half2_rn(lo, hi);
    return *reinterpret_cast<const uint32_t*>(&h);
}
// exp2 of two fp32 values -> packed half2 (one f16x2 MUFU instead of two fp32)
__device__ __forceinline__ uint32_t ex2h2(float lo, float hi) {
    uint32_t h, r;
    asm("cvt.rn.f16x2.f32 %0, %1, %2;" : "=r"(h) : "f"(hi), "f"(lo));
    asm("ex2.approx.f16x2 %0, %1;" : "=r"(r) : "r"(h));
    return r;
}

// ---------------------------------------------------------------------------
// fp16 HMMA GEMM (round-13, byte-identical): C[M,N] = A[M,1024] @ B[N,1024]^T.
// OMODE: 0 fp32 out | 1 RoPE -> fp16 | 2 RoPE+0.125*log2e -> fp16 | 3 V^T fp16
// CTA 128x128, 16 warps (512 thr, warp 32x32), K-chunk 64, double buffer.
// ---------------------------------------------------------------------------
#define GSM_STAGE 32768
#define GSM_TOT   65536

template <int OMODE>
__device__ __forceinline__ void gemm_hmma(
    const __half* __restrict__ A, const __half* __restrict__ B,
    float* __restrict__ Cf, __half* __restrict__ Ch,
    int N, int brow, int bcol,
    const float* __restrict__ fc, const float* __restrict__ fs)
{
    extern __shared__ char gsm[];
    const uint32_t sb = (uint32_t)__cvta_generic_to_shared(gsm);

    const int tid  = threadIdx.x;
    const int wid  = tid >> 5;
    const int lane = tid & 31;
    const int m_base = (wid >> 2) * 32;
    const int n_base = (wid & 3) * 32;

    const int lrow = tid >> 2;                 // 128 rows, 4 thr/row
    const __half* Asrc = A + (size_t)(brow + lrow) * KDIM;
    const __half* Bsrc = B + (size_t)(bcol + lrow) * KDIM;

    float acc[2][4][4];
    #pragma unroll
    for (int mi = 0; mi < 2; ++mi)
        #pragma unroll
        for (int nj = 0; nj < 4; ++nj)
            #pragma unroll
            for (int e = 0; e < 4; ++e) acc[mi][nj][e] = 0.f;

    const int arow0 = (lane & 15);
    const int akoff = (lane >> 4);
    const int brw   = ((lane >> 4) << 3) + (lane & 7);
    const int bkoff = ((lane >> 3) & 1);

    auto load_chunk = [&](int st, int c) {
        const uint32_t stoff = sb + (uint32_t)(st * GSM_STAGE);
        #pragma unroll
        for (int j = 0; j < 2; ++j) {
            const int cc = (tid & 3) * 2 + j;
            const uint32_t sw = (uint32_t)(((cc ^ (lrow & 7)) << 4) + (lrow << 7));
            cp16(stoff +         sw, Asrc + c * 64 + cc * 8);
            cp16(stoff + 16384 + sw, Bsrc + c * 64 + cc * 8);
        }
        asm volatile("cp.async.commit_group;");
    };

    const int NCH = KDIM / 64;   // 16
    load_chunk(0, 0);

    #pragma unroll 1
    for (int c = 0; c < NCH; ++c) {
        const int cur = c & 1;
        if (c + 1 < NCH) {
            load_chunk(cur ^ 1, c + 1);
            asm volatile("cp.async.wait_group 1;");
        } else {
            asm volatile("cp.async.wait_group 0;");
        }
        __syncthreads();
        const uint32_t stoff = sb + (uint32_t)(cur * GSM_STAGE);

        #pragma unroll
        for (int kc = 0; kc < 4; ++kc) {
            uint32_t bf[4][2];
            #pragma unroll
            for (int g = 0; g < 2; ++g) {
                const int r = n_base + g * 16 + brw;
                const uint32_t ch = (uint32_t)((((2 * kc + bkoff) ^ (r & 7)) << 4) +
                                               (r << 7));
                uint32_t t4[4];
                ldsm_x4(t4, stoff + 16384 + ch);
                bf[g * 2][0] = t4[0]; bf[g * 2][1] = t4[1];
                bf[g * 2 + 1][0] = t4[2]; bf[g * 2 + 1][1] = t4[3];
            }
            #pragma unroll
            for (int mi = 0; mi < 2; ++mi) {
                const int r = m_base + mi * 16 + arow0;
                const uint32_t ch = (uint32_t)((((2 * kc + akoff) ^ (r & 7)) << 4) +
                                               (r << 7));
                uint32_t af[4];
                ldsm_x4(af, stoff + ch);
                #pragma unroll
                for (int nj = 0; nj < 4; ++nj)
                    mma16816(acc[mi][nj], af, bf[nj]);
            }
        }
        __syncthreads();
    }

    const int rbase = brow + m_base + (lane >> 2);
    const int cbase = bcol + n_base + (lane & 3) * 2;
    #pragma unroll
    for (int mi = 0; mi < 2; ++mi) {
        #pragma unroll
        for (int half = 0; half < 2; ++half) {
            const int r = rbase + mi * 16 + half * 8;
            const int srow = r & (SEQ - 1);
            #pragma unroll
            for (int nj = 0; nj < 4; ++nj) {
                const int col = cbase + nj * 8;
                float v0 = acc[mi][nj][half * 2];
                float v1 = acc[mi][nj][half * 2 + 1];
                if (OMODE == 1 || OMODE == 2) {
                    const int pair = (col & 63) >> 1;
                    const float cc = fc[srow * 32 + pair];
                    const float ss = fs[srow * 32 + pair];
                    float orv = v0 * cc - v1 * ss;
                    float oiv = v0 * ss + v1 * cc;
                    if (OMODE == 2) {
                        // 0.125 * log2(e): fold 1/sqrt(d) + exp2 conversion
                        orv *= 0.1803368801111244f; oiv *= 0.1803368801111244f;
                    }
                    const __half2 hv = __floats2half2_rn(orv, oiv);
                    *reinterpret_cast<__half2*>(Ch + (size_t)r * N + col) = hv;
                } else if (OMODE == 3) {
                    // V^T: dst[(b*4+hk)*64 + d][s]
                    const int b  = r >> 11;
                    const int s  = r & (SEQ - 1);
                    const int hk = col >> 6;
                    const int d  = col & 63;
                    __half* dst = Ch + ((size_t)((b * 4 + hk) * 64 + d)) * SEQ + s;
                    dst[0]   = __float2half(v0);
                    dst[SEQ] = __float2half(v1);
                } else {
                    *reinterpret_cast<float2*>(Cf + (size_t)r * N + col) = make_float2(v0, v1);
                }
            }
        }
    }
}

// Fused QKV: bx 0-7 Q (+RoPE+scale), 8-9 K (+RoPE), 10-11 V (->V^T)
__global__ void __launch_bounds__(512, 2) qkv_hmma_kernel(
    const float* __restrict__ fc, const float* __restrict__ fs)
{
    const int bx   = blockIdx.x;
    const int brow = blockIdx.y * 128;
    if (bx < 8)
        gemm_hmma<2>(g_xh, g_wqt, nullptr, g_qh, 1024, brow, bx * 128, fc, fs);
    else if (bx < 10)
        gemm_hmma<1>(g_xh, g_wkt, nullptr, g_kh, 256, brow, (bx - 8) * 128, fc, fs);
    else
        gemm_hmma<3>(g_xh, g_wvt, nullptr, g_vth, 256, brow, (bx - 10) * 128, nullptr, nullptr);
}

__global__ void __launch_bounds__(512, 2) oproj_hmma_kernel(float* __restrict__ out)
{
    gemm_hmma<0>(g_oh, g_wot, out, nullptr, 1024,
                 blockIdx.y * 128, blockIdx.x * 128, nullptr, nullptr);
}

// ---------------------------------------------------------------------------
// Fused prep: [0,4096) x->fp16 | then wq, wk, wv, wo transpose->fp16
// ---------------------------------------------------------------------------
__device__ __forceinline__ void wconv_body(
    const float* __restrict__ W, __half* __restrict__ T, int N, int n0, int k0)
{
    __shared__ float t[32][33];
    const int tx = threadIdx.x & 31, ty = threadIdx.x >> 5;
    #pragma unroll
    for (int i = 0; i < 32; i += 8)
        t[ty + i][tx] = W[(size_t)(k0 + ty + i) * N + n0 + tx];
    __syncthreads();
    #pragma unroll
    for (int i = 0; i < 32; i += 8)
        T[(size_t)(n0 + ty + i) * 1024 + k0 + tx] = __float2half(t[tx][ty + i]);
}

__global__ void __launch_bounds__(256) prep_kernel(
    const float* __restrict__ x,
    const float* __restrict__ wq, const float* __restrict__ wk,
    const float* __restrict__ wv, const float* __restrict__ wo)
{
    const int bid = blockIdx.x;
    if (bid < 4096) {
        const int i = bid * 256 + threadIdx.x;
        const float4 v = reinterpret_cast<const float4*>(x)[i];
        uint2 st;
        st.x = pack_f16(v.x, v.y);
        st.y = pack_f16(v.z, v.w);
        reinterpret_cast<uint2*>(g_xh)[i] = st;
    } else if (bid < 5120) {
        const int i = bid - 4096;
        wconv_body(wq, g_wqt, 1024, (i & 31) * 32, (i >> 5) * 32);
    } else if (bid < 5376) {
        const int i = bid - 5120;
        wconv_body(wk, g_wkt, 256, (i & 7) * 32, (i >> 3) * 32);
    } else if (bid < 5632) {
        const int i = bid - 5376;
        wconv_body(wv, g_wvt, 256, (i & 7) * 32, (i >> 3) * 32);
    } else {
        const int i = bid - 5632;
        wconv_body(wo, g_wot, 1024, (i & 31) * 32, (i >> 5) * 32);
    }
}

// ---------------------------------------------------------------------------
// Tensor-core flash attention (fp16, exp2 domain, f16x2 MUFU softmax).
// CTA = 128 queries x (b,h). 8 warps x 16 query rows (256 threads).
// K-tiles of 128 keys per cp.async stage, processed as two 64-key sub-blocks
// with NO barrier between them (sub1 ldsm/S-MMAs overlap sub0 softmax bubble).
// Stage layout: [Ksub0 8K][Ksub1 8K][Vsub0 8K][Vsub1 8K] = 32K.
// smem: Q 16K | 2 stages x 32K = 80K dynamic; 2 CTA/SM.
// l via ones-vector HMMA (exact row sums, no shfl reduction).
// ---------------------------------------------------------------------------
#define ASM_Q   0
#define ASM_ST  16384
#define ASM_STAGE 32768
#define ASM_TOT (16384 + 2 * 32768)

__global__ void __launch_bounds__(256, 2) attn_mma_kernel()
{
    extern __shared__ char asmem[];
    const uint32_t sb = (uint32_t)__cvta_generic_to_shared(asmem);
    const int tid = threadIdx.x, w = tid >> 5, lane = tid & 31;
    const int b = blockIdx.z, h = blockIdx.y;
    const int qt = (int)gridDim.x - 1 - blockIdx.x;   // heavy tiles first
    const int hk = h >> 2;
    const int q0 = qt * 128;
    const int ntiles = qt + 1;                        // 128-key tiles

    // --- Q tile load (once): 128 rows x 64 d ---
    {
        const int row = tid >> 1;
        const size_t qoff = (size_t)(b * SEQ + q0 + row) * 1024 + h * 64;
        #pragma unroll
        for (int j = 0; j < 4; ++j) {
            const int c = (tid & 1) * 4 + j;
            const uint32_t sw = (uint32_t)((c ^ (row & 7)) << 4) + (uint32_t)(row << 7);
            cp16(sb + ASM_Q + sw, g_qh + qoff + c * 8);
        }
        asm volatile("cp.async.commit_group;");
    }
    // stage loader: 128 keys = 2 sub-tiles of (K 64x128B, V^T 64x128B)
    auto load_stage = [&](int st, int kt) {
        const int row = tid >> 2;                    // 64 rows
        const uint32_t so = sb + ASM_ST + (uint32_t)st * ASM_STAGE;
        #pragma unroll
        for (int sub = 0; sub < 2; ++sub) {
            const int kbase = kt * 128 + sub * 64;
            const size_t koff = (size_t)(b * SEQ + kbase + row) * 256 + hk * 64;
            const size_t voff = (size_t)((b * 4 + hk) * 64 + row) * SEQ + kbase;
            const uint32_t sk = so + (uint32_t)(sub * 8192);
            const uint32_t sv = so + 16384u + (uint32_t)(sub * 8192);
            #pragma unroll
            for (int i = 0; i < 2; ++i) {
                const int c = (tid & 3) * 2 + i;
                const uint32_t sw = (uint32_t)((c ^ (row & 7)) << 4) + (uint32_t)(row << 7);
                cp16(sk + sw, g_kh + koff + c * 8);
                cp16(sv + sw, g_vth + voff + c * 8);
            }
        }
        asm volatile("cp.async.commit_group;");
    };
    load_stage(0, 0);

    const int arow = lane & 15, akoff = lane >> 4;
    const int brw  = ((lane >> 4) << 3) + (lane & 7);
    const int bkoff = (lane >> 3) & 1;

    // --- hoist Q fragments (warp owns rows w*16 .. w*16+15) ---
    asm volatile("cp.async.wait_group 1;");
    __syncthreads();
    uint32_t qf[4][4];
    #pragma unroll
    for (int kc = 0; kc < 4; ++kc) {
        const int r = w * 16 + arow;
        const uint32_t ch = (uint32_t)(((2 * kc + akoff) ^ (r & 7)) << 4) +
                            (uint32_t)(r << 7);
        ldsm_x4(qf[kc], sb + ASM_Q + ch);
    }

    float o[8][4];
    #pragma unroll
    for (int nj = 0; nj < 8; ++nj)
        #pragma unroll
        for (int e = 0; e < 4; ++e) o[nj][e] = 0.f;
    float lacc[4] = {0.f, 0.f, 0.f, 0.f};           // row-sum accum via ones-MMA
    float mrow[2] = {-1e30f, -1e30f};
    const uint32_t ones2[2] = {0x3C003C00u, 0x3C003C00u};  // f16 1.0 x4
    const int qwbase = q0 + w * 16;

    #pragma unroll 1
    for (int kt = 0; kt < ntiles; ++kt) {
        const int st = kt & 1;
        if (kt + 1 < ntiles) {
            load_stage(st ^ 1, kt + 1);
            asm volatile("cp.async.wait_group 1;");
        } else {
            asm volatile("cp.async.wait_group 0;");
        }
        __syncthreads();
        const uint32_t so = sb + ASM_ST + (uint32_t)st * ASM_STAGE;

        #pragma unroll
        for (int sub = 0; sub < 2; ++sub) {
            const uint32_t sk = so + (uint32_t)(sub * 8192);
            const uint32_t sv = so + 16384u + (uint32_t)(sub * 8192);
            const int kbase = kt * 128 + sub * 64;

            // ---- S = Q @ K^T (scores already in log2 domain) ----
            float sc[8][4];
            #pragma unroll
            for (int nj = 0; nj < 8; ++nj)
                #pragma unroll
                for (int e = 0; e < 4; ++e) sc[nj][e] = 0.f;

            #pragma unroll
            for (int kc = 0; kc < 4; ++kc) {
                uint32_t kb[8][2];
                #pragma unroll
                for (int g = 0; g < 4; ++g) {
                    const int r = g * 16 + brw;
                    const uint32_t ch = (uint32_t)(((2 * kc + bkoff) ^ (r & 7)) << 4) +
                                        (uint32_t)(r << 7);
                    uint32_t t4[4];
                    ldsm_x4(t4, sk + ch);
                    kb[g * 2][0] = t4[0]; kb[g * 2][1] = t4[1];
                    kb[g * 2 + 1][0] = t4[2]; kb[g * 2 + 1][1] = t4[3];
                }
                #pragma unroll
                for (int nj = 0; nj < 8; ++nj)
                    mma16816(sc[nj], qf[kc], kb[nj]);
            }

            // ---- causal mask (partial tiles only) ----
            if (kbase + 63 > qwbase) {
                const int jb = kbase + (lane & 3) * 2;
                const int qb = qwbase + (lane >> 2);
                #pragma unroll
                for (int nj = 0; nj < 8; ++nj)
                    #pragma unroll
                    for (int e = 0; e < 4; ++e) {
                        const int j = jb + nj * 8 + (e & 1);
                        const int q = qb + ((e >> 1) << 3);
                        if (j > q) sc[nj][e] = -1e30f;
                    }
            }

            // ---- online softmax (base-2) max/rescale ----
            float tm[2] = {-1e30f, -1e30f};
            #pragma unroll
            for (int nj = 0; nj < 8; ++nj)
                #pragma unroll
                for (int e = 0; e < 4; ++e)
                    tm[e >> 1] = fmaxf(tm[e >> 1], sc[nj][e]);
            float alpha[2];
            #pragma unroll
            for (int ri = 0; ri < 2; ++ri) {
                tm[ri] = fmaxf(tm[ri], __shfl_xor_sync(0xffffffffu, tm[ri], 1));
                tm[ri] = fmaxf(tm[ri], __shfl_xor_sync(0xffffffffu, tm[ri], 2));
                const float nm = fmaxf(mrow[ri], tm[ri]);
                alpha[ri] = exp2f(mrow[ri] - nm);
                mrow[ri] = nm;
            }
            const bool chg = (alpha[0] < 1.f) || (alpha[1] < 1.f);
            if (__any_sync(0xffffffffu, chg)) {
                #pragma unroll
                for (int nj = 0; nj < 8; ++nj) {
                    o[nj][0] *= alpha[0]; o[nj][1] *= alpha[0];
                    o[nj][2] *= alpha[1]; o[nj][3] *= alpha[1];
                }
                lacc[0] *= alpha[0]; lacc[1] *= alpha[0];
                lacc[2] *= alpha[1]; lacc[3] *= alpha[1];
            }

            // ---- p = exp2(s-m) packed half2 (f16x2 MUFU); l += P @ ones ----
            uint32_t ap[4][4];
            #pragma unroll
            for (int kc = 0; kc < 4; ++kc) {
                const float* s0 = sc[2 * kc];
                const float* s1 = sc[2 * kc + 1];
                ap[kc][0] = ex2h2(s0[0] - mrow[0], s0[1] - mrow[0]);
                ap[kc][1] = ex2h2(s0[2] - mrow[1], s0[3] - mrow[1]);
                ap[kc][2] = ex2h2(s1[0] - mrow[0], s1[1] - mrow[0]);
                ap[kc][3] = ex2h2(s1[2] - mrow[1], s1[3] - mrow[1]);
                mma16816(lacc, ap[kc], ones2);
            }

            // ---- O += P @ V ----
            #pragma unroll
            for (int kc = 0; kc < 4; ++kc) {
                uint32_t vb[8][2];
                #pragma unroll
                for (int g = 0; g < 4; ++g) {
                    const int r = g * 16 + brw;
                    const uint32_t ch = (uint32_t)(((2 * kc + bkoff) ^ (r & 7)) << 4) +
                                        (uint32_t)(r << 7);
                    uint32_t t4[4];
                    ldsm_x4(t4, sv + ch);
                    vb[g * 2][0] = t4[0]; vb[g * 2][1] = t4[1];
                    vb[g * 2 + 1][0] = t4[2]; vb[g * 2 + 1][1] = t4[3];
                }
                #pragma unroll
                for (int nj = 0; nj < 8; ++nj)
                    mma16816(o[nj], ap[kc], vb[nj]);
            }
        }
        __syncthreads();
    }

    // ---- epilogue: normalize + write fp16 (lacc holds exact row sums) ----
    const float linv[2] = {1.0f / lacc[0], 1.0f / lacc[2]};
    #pragma unroll
    for (int half = 0; half < 2; ++half) {
        const int rloc = w * 16 + (lane >> 2) + half * 8;
        const size_t rg = (size_t)(b * SEQ + q0 + rloc) * 1024 + h * 64;
        const float inv = linv[half];
        #pragma unroll
        for (int nj = 0; nj < 8; ++nj) {
            const int col = nj * 8 + (lane & 3) * 2;
            const __half2 hv = __floats2half2_rn(o[nj][half * 2] * inv,
                                                 o[nj][half * 2 + 1] * inv);
            *reinterpret_cast<__half2*>(g_oh + rg + col) = hv;
        }
    }
}

// ---------------------------------------------------------------------------
// Inputs: x, start_pos, freqs_cos, freqs_sin, mask, wq, wk, wv, wo
// ---------------------------------------------------------------------------
extern "C" void kernel_launch(void* const* d_in, const int* in_sizes, int n_in,
                              void* d_out, int out_size)
{
    const float* x  = (const float*)d_in[0];
    const float* fc = (const float*)d_in[2];
    const float* fs = (const float*)d_in[3];
    const float* wq = (const float*)d_in[5];
    const float* wk = (const float*)d_in[6];
    const float* wv = (const float*)d_in[7];
    const float* wo = (const float*)d_in[8];
    float* out = (float*)d_out;

    cudaFuncSetAttribute(qkv_hmma_kernel,
                         cudaFuncAttributeMaxDynamicSharedMemorySize, GSM_TOT);
    cudaFuncSetAttribute(oproj_hmma_kernel,
                         cudaFuncAttributeMaxDynamicSharedMemorySize, GSM_TOT);
    cudaFuncSetAttribute(attn_mma_kernel,
                         cudaFuncAttributeMaxDynamicSharedMemorySize, ASM_TOT);

    // Fused prep: x -> fp16; weights -> transposed fp16
    prep_kernel<<<6656, 256>>>(x, wq, wk, wv, wo);
    // QKV projection (fp16 HMMA, 512 thr; Q/K RoPE'd fp16; V written transposed)
    qkv_hmma_kernel<<<dim3(12, 32), 512, GSM_TOT>>>(fc, fs);
    // Tensor-core flash attention (256 thr, 128-key stages)
    attn_mma_kernel<<<dim3(16, 16, 2), 256, ASM_TOT>>>();
    // Output projection -> d_out (fp32)
    oproj_hmma_kernel<<<dim3(8, 32), 512, GSM_TOT>>>(out);
}

// round 15
// speedup vs baseline: 1.6307x; 1.0115x over previous
#include <cuda_runtime.h>
#include <cuda_fp16.h>
#include <cstddef>
#include <cstdint>

#define SEQ    2048
#define KDIM   1024

// ---------------------------------------------------------------------------
// Device scratch (no allocation allowed)
// ---------------------------------------------------------------------------
__device__ __half g_xh[4096 * 1024];                 // x fp16
__device__ __half g_wqt[1024 * 1024];                // W^T [N,K] fp16
__device__ __half g_wkt[256 * 1024];
__device__ __half g_wvt[256 * 1024];
__device__ __half g_wot[1024 * 1024];
__device__ __half g_qh[4096 * 1024];                 // Q RoPE'd, ×0.125·log2e
__device__ __half g_kh[4096 * 256];                  // K RoPE'd
__device__ __half g_vth[8 * 64 * 2048];              // V^T [(b*4+hk)][d][s]
__device__ __half g_oh[4096 * 1024];                 // attention out

// ---------------------------------------------------------------------------
// PTX helpers (architecture-generic; plain sm_103 target)
// ---------------------------------------------------------------------------
__device__ __forceinline__ void ldsm_x4(uint32_t r[4], uint32_t addr) {
    asm volatile("ldmatrix.sync.aligned.m8n8.x4.shared.b16 {%0,%1,%2,%3}, [%4];"
        : "=r"(r[0]), "=r"(r[1]), "=r"(r[2]), "=r"(r[3]) : "r"(addr));
}
__device__ __forceinline__ void mma16816(float c[4], const uint32_t a[4], const uint32_t b[2]) {
    asm volatile(
        "mma.sync.aligned.m16n8k16.row.col.f32.f16.f16.f32 "
        "{%0,%1,%2,%3}, {%4,%5,%6,%7}, {%8,%9}, {%0,%1,%2,%3};"
        : "+f"(c[0]), "+f"(c[1]), "+f"(c[2]), "+f"(c[3])
        : "r"(a[0]), "r"(a[1]), "r"(a[2]), "r"(a[3]), "r"(b[0]), "r"(b[1]));
}
__device__ __forceinline__ void cp16(uint32_t dst, const void* src) {
    asm volatile("cp.async.cg.shared.global [%0], [%1], 16;" :: "r"(dst), "l"(src));
}
__device__ __forceinline__ uint32_t pack_f16(float lo, float hi) {
    const __half2 h = __floats2half2_rn(lo, hi);
    return *reinterpret_cast<const uint32_t*>(&h);
}
// exp2 of two fp32 values -> packed half2 (one f16x2 MUFU instead of two fp32)
__device__ __forceinline__ uint32_t ex2h2(float lo, float hi) {
    uint32_t h, r;
    asm("cvt.rn.f16x2.f32 %0, %1, %2;" : "=r"(h) : "f"(hi), "f"(lo));
    asm("ex2.approx.f16x2 %0, %1;" : "=r"(r) : "r"(h));
    return r;
}

// ---------------------------------------------------------------------------
// fp16 HMMA GEMM (round-13, byte-identical): C[M,N] = A[M,1024] @ B[N,1024]^T.
// OMODE: 0 fp32 out | 1 RoPE -> fp16 | 2 RoPE+0.125*log2e -> fp16 | 3 V^T fp16
// CTA 128x128, 16 warps (512 thr, warp 32x32), K-chunk 64, double buffer.
// ---------------------------------------------------------------------------
#define GSM_STAGE 32768
#define GSM_TOT   65536

template <int OMODE>
__device__ __forceinline__ void gemm_hmma(
    const __half* __restrict__ A, const __half* __restrict__ B,
    float* __restrict__ Cf, __half* __restrict__ Ch,
    int N, int brow, int bcol,
    const float* __restrict__ fc, const float* __restrict__ fs)
{
    extern __shared__ char gsm[];
    const uint32_t sb = (uint32_t)__cvta_generic_to_shared(gsm);

    const int tid  = threadIdx.x;
    const int wid  = tid >> 5;
    const int lane = tid & 31;
    const int m_base = (wid >> 2) * 32;
    const int n_base = (wid & 3) * 32;

    const int lrow = tid >> 2;                 // 128 rows, 4 thr/row
    const __half* Asrc = A + (size_t)(brow + lrow) * KDIM;
    const __half* Bsrc = B + (size_t)(bcol + lrow) * KDIM;

    float acc[2][4][4];
    #pragma unroll
    for (int mi = 0; mi < 2; ++mi)
        #pragma unroll
        for (int nj = 0; nj < 4; ++nj)
            #pragma unroll
            for (int e = 0; e < 4; ++e) acc[mi][nj][e] = 0.f;

    const int arow0 = (lane & 15);
    const int akoff = (lane >> 4);
    const int brw   = ((lane >> 4) << 3) + (lane & 7);
    const int bkoff = ((lane >> 3) & 1);

    auto load_chunk = [&](int st, int c) {
        const uint32_t stoff = sb + (uint32_t)(st * GSM_STAGE);
        #pragma unroll
        for (int j = 0; j < 2; ++j) {
            const int cc = (tid & 3) * 2 + j;
            const uint32_t sw = (uint32_t)(((cc ^ (lrow & 7)) << 4) + (lrow << 7));
            cp16(stoff +         sw, Asrc + c * 64 + cc * 8);
            cp16(stoff + 16384 + sw, Bsrc + c * 64 + cc * 8);
        }
        asm volatile("cp.async.commit_group;");
    };

    const int NCH = KDIM / 64;   // 16
    load_chunk(0, 0);

    #pragma unroll 1
    for (int c = 0; c < NCH; ++c) {
        const int cur = c & 1;
        if (c + 1 < NCH) {
            load_chunk(cur ^ 1, c + 1);
            asm volatile("cp.async.wait_group 1;");
        } else {
            asm volatile("cp.async.wait_group 0;");
        }
        __syncthreads();
        const uint32_t stoff = sb + (uint32_t)(cur * GSM_STAGE);

        #pragma unroll
        for (int kc = 0; kc < 4; ++kc) {
            uint32_t bf[4][2];
            #pragma unroll
            for (int g = 0; g < 2; ++g) {
                const int r = n_base + g * 16 + brw;
                const uint32_t ch = (uint32_t)((((2 * kc + bkoff) ^ (r & 7)) << 4) +
                                               (r << 7));
                uint32_t t4[4];
                ldsm_x4(t4, stoff + 16384 + ch);
                bf[g * 2][0] = t4[0]; bf[g * 2][1] = t4[1];
                bf[g * 2 + 1][0] = t4[2]; bf[g * 2 + 1][1] = t4[3];
            }
            #pragma unroll
            for (int mi = 0; mi < 2; ++mi) {
                const int r = m_base + mi * 16 + arow0;
                const uint32_t ch = (uint32_t)((((2 * kc + akoff) ^ (r & 7)) << 4) +
                                               (r << 7));
                uint32_t af[4];
                ldsm_x4(af, stoff + ch);
                #pragma unroll
                for (int nj = 0; nj < 4; ++nj)
                    mma16816(acc[mi][nj], af, bf[nj]);
            }
        }
        __syncthreads();
    }

    const int rbase = brow + m_base + (lane >> 2);
    const int cbase = bcol + n_base + (lane & 3) * 2;
    #pragma unroll
    for (int mi = 0; mi < 2; ++mi) {
        #pragma unroll
        for (int half = 0; half < 2; ++half) {
            const int r = rbase + mi * 16 + half * 8;
            const int srow = r & (SEQ - 1);
            #pragma unroll
            for (int nj = 0; nj < 4; ++nj) {
                const int col = cbase + nj * 8;
                float v0 = acc[mi][nj][half * 2];
                float v1 = acc[mi][nj][half * 2 + 1];
                if (OMODE == 1 || OMODE == 2) {
                    const int pair = (col & 63) >> 1;
                    const float cc = fc[srow * 32 + pair];
                    const float ss = fs[srow * 32 + pair];
                    float orv = v0 * cc - v1 * ss;
                    float oiv = v0 * ss + v1 * cc;
                    if (OMODE == 2) {
                        // 0.125 * log2(e): fold 1/sqrt(d) + exp2 conversion
                        orv *= 0.1803368801111244f; oiv *= 0.1803368801111244f;
                    }
                    const __half2 hv = __floats2half2_rn(orv, oiv);
                    *reinterpret_cast<__half2*>(Ch + (size_t)r * N + col) = hv;
                } else if (OMODE == 3) {
                    // V^T: dst[(b*4+hk)*64 + d][s]
                    const int b  = r >> 11;
                    const int s  = r & (SEQ - 1);
                    const int hk = col >> 6;
                    const int d  = col & 63;
                    __half* dst = Ch + ((size_t)((b * 4 + hk) * 64 + d)) * SEQ + s;
                    dst[0]   = __float2half(v0);
                    dst[SEQ] = __float2half(v1);
                } else {
                    *reinterpret_cast<float2*>(Cf + (size_t)r * N + col) = make_float2(v0, v1);
                }
            }
        }
    }
}

// Fused QKV: bx 0-7 Q (+RoPE+scale), 8-9 K (+RoPE), 10-11 V (->V^T)
__global__ void __launch_bounds__(512, 2) qkv_hmma_kernel(
    const float* __restrict__ fc, const float* __restrict__ fs)
{
    const int bx   = blockIdx.x;
    const int brow = blockIdx.y * 128;
    if (bx < 8)
        gemm_hmma<2>(g_xh, g_wqt, nullptr, g_qh, 1024, brow, bx * 128, fc, fs);
    else if (bx < 10)
        gemm_hmma<1>(g_xh, g_wkt, nullptr, g_kh, 256, brow, (bx - 8) * 128, fc, fs);
    else
        gemm_hmma<3>(g_xh, g_wvt, nullptr, g_vth, 256, brow, (bx - 10) * 128, nullptr, nullptr);
}

__global__ void __launch_bounds__(512, 2) oproj_hmma_kernel(float* __restrict__ out)
{
    gemm_hmma<0>(g_oh, g_wot, out, nullptr, 1024,
                 blockIdx.y * 128, blockIdx.x * 128, nullptr, nullptr);
}

// ---------------------------------------------------------------------------
// Fused prep, MLP-optimized:
//   blocks [0,1024): x -> fp16, 4 independent float4 loads per thread
//   blocks [1024,...): weight transpose -> fp16, batched row loads (MLP=4)
// ---------------------------------------------------------------------------
__device__ __forceinline__ void wconv_body(
    const float* __restrict__ W, __half* __restrict__ T, int N, int n0, int k0)
{
    __shared__ float t[32][33];
    const int tx = threadIdx.x & 31, ty = threadIdx.x >> 5;
    // batch all 4 global loads (independent -> MLP 4)
    float v[4];
    #pragma unroll
    for (int i = 0; i < 4; ++i)
        v[i] = W[(size_t)(k0 + ty + i * 8) * N + n0 + tx];
    #pragma unroll
    for (int i = 0; i < 4; ++i)
        t[ty + i * 8][tx] = v[i];
    __syncthreads();
    float o[4];
    #pragma unroll
    for (int i = 0; i < 4; ++i)
        o[i] = t[tx][ty + i * 8];
    #pragma unroll
    for (int i = 0; i < 4; ++i)
        T[(size_t)(n0 + ty + i * 8) * 1024 + k0 + tx] = __float2half(o[i]);
}

__global__ void __launch_bounds__(256) prep_kernel(
    const float* __restrict__ x,
    const float* __restrict__ wq, const float* __restrict__ wk,
    const float* __restrict__ wv, const float* __restrict__ wo)
{
    const int bid = blockIdx.x;
    if (bid < 1024) {
        // x conversion: 4 independent float4 per thread (MLP=4)
        const int i0 = bid * 1024 + threadIdx.x;   // over 1M float4s, stride 256
        float4 v[4];
        #pragma unroll
        for (int j = 0; j < 4; ++j)
            v[j] = reinterpret_cast<const float4*>(x)[i0 + j * 256];
        #pragma unroll
        for (int j = 0; j < 4; ++j) {
            uint2 st;
            st.x = pack_f16(v[j].x, v[j].y);
            st.y = pack_f16(v[j].z, v[j].w);
            reinterpret_cast<uint2*>(g_xh)[i0 + j * 256] = st;
        }
    } else if (bid < 2048) {
        const int i = bid - 1024;
        wconv_body(wq, g_wqt, 1024, (i & 31) * 32, (i >> 5) * 32);
    } else if (bid < 2304) {
        const int i = bid - 2048;
        wconv_body(wk, g_wkt, 256, (i & 7) * 32, (i >> 3) * 32);
    } else if (bid < 2560) {
        const int i = bid - 2304;
        wconv_body(wv, g_wvt, 256, (i & 7) * 32, (i >> 3) * 32);
    } else {
        const int i = bid - 2560;
        wconv_body(wo, g_wot, 1024, (i & 31) * 32, (i >> 5) * 32);
    }
}

// ---------------------------------------------------------------------------
// Tensor-core flash attention (round-14, byte-identical).
// fp16, exp2 domain, f16x2 MUFU softmax. CTA = 128 queries x (b,h).
// 8 warps x 16 query rows (256 threads). 128-key stages, two 64-key
// sub-blocks per stage with no intervening barrier.
// smem: Q 16K | 2 stages x 32K = 80K dynamic; 2 CTA/SM.
// ---------------------------------------------------------------------------
#define ASM_Q   0
#define ASM_ST  16384
#define ASM_STAGE 32768
#define ASM_TOT (16384 + 2 * 32768)

__global__ void __launch_bounds__(256, 2) attn_mma_kernel()
{
    extern __shared__ char asmem[];
    const uint32_t sb = (uint32_t)__cvta_generic_to_shared(asmem);
    const int tid = threadIdx.x, w = tid >> 5, lane = tid & 31;
    const int b = blockIdx.z, h = blockIdx.y;
    const int qt = (int)gridDim.x - 1 - blockIdx.x;   // heavy tiles first
    const int hk = h >> 2;
    const int q0 = qt * 128;
    const int ntiles = qt + 1;                        // 128-key tiles

    // --- Q tile load (once): 128 rows x 64 d ---
    {
        const int row = tid >> 1;
        const size_t qoff = (size_t)(b * SEQ + q0 + row) * 1024 + h * 64;
        #pragma unroll
        for (int j = 0; j < 4; ++j) {
            const int c = (tid & 1) * 4 + j;
            const uint32_t sw = (uint32_t)((c ^ (row & 7)) << 4) + (uint32_t)(row << 7);
            cp16(sb + ASM_Q + sw, g_qh + qoff + c * 8);
        }
        asm volatile("cp.async.commit_group;");
    }
    // stage loader: 128 keys = 2 sub-tiles of (K 64x128B, V^T 64x128B)
    auto load_stage = [&](int st, int kt) {
        const int row = tid >> 2;                    // 64 rows
        const uint32_t so = sb + ASM_ST + (uint32_t)st * ASM_STAGE;
        #pragma unroll
        for (int sub = 0; sub < 2; ++sub) {
            const int kbase = kt * 128 + sub * 64;
            const size_t koff = (size_t)(b * SEQ + kbase + row) * 256 + hk * 64;
            const size_t voff = (size_t)((b * 4 + hk) * 64 + row) * SEQ + kbase;
            const uint32_t sk = so + (uint32_t)(sub * 8192);
            const uint32_t sv = so + 16384u + (uint32_t)(sub * 8192);
            #pragma unroll
            for (int i = 0; i < 2; ++i) {
                const int c = (tid & 3) * 2 + i;
                const uint32_t sw = (uint32_t)((c ^ (row & 7)) << 4) + (uint32_t)(row << 7);
                cp16(sk + sw, g_kh + koff + c * 8);
                cp16(sv + sw, g_vth + voff + c * 8);
            }
        }
        asm volatile("cp.async.commit_group;");
    };
    load_stage(0, 0);

    const int arow = lane & 15, akoff = lane >> 4;
    const int brw  = ((lane >> 4) << 3) + (lane & 7);
    const int bkoff = (lane >> 3) & 1;

    // --- hoist Q fragments (warp owns rows w*16 .. w*16+15) ---
    asm volatile("cp.async.wait_group 1;");
    __syncthreads();
    uint32_t qf[4][4];
    #pragma unroll
    for (int kc = 0; kc < 4; ++kc) {
        const int r = w * 16 + arow;
        const uint32_t ch = (uint32_t)(((2 * kc + akoff) ^ (r & 7)) << 4) +
                            (uint32_t)(r << 7);
        ldsm_x4(qf[kc], sb + ASM_Q + ch);
    }

    float o[8][4];
    #pragma unroll
    for (int nj = 0; nj < 8; ++nj)
        #pragma unroll
        for (int e = 0; e < 4; ++e) o[nj][e] = 0.f;
    float lacc[4] = {0.f, 0.f, 0.f, 0.f};           // row-sum accum via ones-MMA
    float mrow[2] = {-1e30f, -1e30f};
    const uint32_t ones2[2] = {0x3C003C00u, 0x3C003C00u};  // f16 1.0 x4
    const int qwbase = q0 + w * 16;

    #pragma unroll 1
    for (int kt = 0; kt < ntiles; ++kt) {
        const int st = kt & 1;
        if (kt + 1 < ntiles) {
            load_stage(st ^ 1, kt + 1);
            asm volatile("cp.async.wait_group 1;");
        } else {
            asm volatile("cp.async.wait_group 0;");
        }
        __syncthreads();
        const uint32_t so = sb + ASM_ST + (uint32_t)st * ASM_STAGE;

        #pragma unroll
        for (int sub = 0; sub < 2; ++sub) {
            const uint32_t sk = so + (uint32_t)(sub * 8192);
            const uint32_t sv = so + 16384u + (uint32_t)(sub * 8192);
            const int kbase = kt * 128 + sub * 64;

            // ---- S = Q @ K^T (scores already in log2 domain) ----
            float sc[8][4];
            #pragma unroll
            for (int nj = 0; nj < 8; ++nj)
                #pragma unroll
                for (int e = 0; e < 4; ++e) sc[nj][e] = 0.f;

            #pragma unroll
            for (int kc = 0; kc < 4; ++kc) {
                uint32_t kb[8][2];
                #pragma unroll
                for (int g = 0; g < 4; ++g) {
                    const int r = g * 16 + brw;
                    const uint32_t ch = (uint32_t)(((2 * kc + bkoff) ^ (r & 7)) << 4) +
                                        (uint32_t)(r << 7);
                    uint32_t t4[4];
                    ldsm_x4(t4, sk + ch);
                    kb[g * 2][0] = t4[0]; kb[g * 2][1] = t4[1];
                    kb[g * 2 + 1][0] = t4[2]; kb[g * 2 + 1][1] = t4[3];
                }
                #pragma unroll
                for (int nj = 0; nj < 8; ++nj)
                    mma16816(sc[nj], qf[kc], kb[nj]);
            }

            // ---- causal mask (partial tiles only) ----
            if (kbase + 63 > qwbase) {
                const int jb = kbase + (lane & 3) * 2;
                const int qb = qwbase + (lane >> 2);
                #pragma unroll
                for (int nj = 0; nj < 8; ++nj)
                    #pragma unroll
                    for (int e = 0; e < 4; ++e) {
                        const int j = jb + nj * 8 + (e & 1);
                        const int q = qb + ((e >> 1) << 3);
                        if (j > q) sc[nj][e] = -1e30f;
                    }
            }

            // ---- online softmax (base-2) max/rescale ----
            float tm[2] = {-1e30f, -1e30f};
            #pragma unroll
            for (int nj = 0; nj < 8; ++nj)
                #pragma unroll
                for (int e = 0; e < 4; ++e)
                    tm[e >> 1] = fmaxf(tm[e >> 1], sc[nj][e]);
            float alpha[2];
            #pragma unroll
            for (int ri = 0; ri < 2; ++ri) {
                tm[ri] = fmaxf(tm[ri], __shfl_xor_sync(0xffffffffu, tm[ri], 1));
                tm[ri] = fmaxf(tm[ri], __shfl_xor_sync(0xffffffffu, tm[ri], 2));
                const float nm = fmaxf(mrow[ri], tm[ri]);
                alpha[ri] = exp2f(mrow[ri] - nm);
                mrow[ri] = nm;
            }
            const bool chg = (alpha[0] < 1.f) || (alpha[1] < 1.f);
            if (__any_sync(0xffffffffu, chg)) {
                #pragma unroll
                for (int nj = 0; nj < 8; ++nj) {
                    o[nj][0] *= alpha[0]; o[nj][1] *= alpha[0];
                    o[nj][2] *= alpha[1]; o[nj][3] *= alpha[1];
                }
                lacc[0] *= alpha[0]; lacc[1] *= alpha[0];
                lacc[2] *= alpha[1]; lacc[3] *= alpha[1];
            }

            // ---- p = exp2(s-m) packed half2 (f16x2 MUFU); l += P @ ones ----
            uint32_t ap[4][4];
            #pragma unroll
            for (int kc = 0; kc < 4; ++kc) {
                const float* s0 = sc[2 * kc];
                const float* s1 = sc[2 * kc + 1];
                ap[kc][0] = ex2h2(s0[0] - mrow[0], s0[1] - mrow[0]);
                ap[kc][1] = ex2h2(s0[2] - mrow[1], s0[3] - mrow[1]);
                ap[kc][2] = ex2h2(s1[0] - mrow[0], s1[1] - mrow[0]);
                ap[kc][3] = ex2h2(s1[2] - mrow[1], s1[3] - mrow[1]);
                mma16816(lacc, ap[kc], ones2);
            }

            // ---- O += P @ V ----
            #pragma unroll
            for (int kc = 0; kc < 4; ++kc) {
                uint32_t vb[8][2];
                #pragma unroll
                for (int g = 0; g < 4; ++g) {
                    const int r = g * 16 + brw;
                    const uint32_t ch = (uint32_t)(((2 * kc + bkoff) ^ (r & 7)) << 4) +
                                        (uint32_t)(r << 7);
                    uint32_t t4[4];
                    ldsm_x4(t4, sv + ch);
                    vb[g * 2][0] = t4[0]; vb[g * 2][1] = t4[1];
                    vb[g * 2 + 1][0] = t4[2]; vb[g * 2 + 1][1] = t4[3];
                }
                #pragma unroll
                for (int nj = 0; nj < 8; ++nj)
                    mma16816(o[nj], ap[kc], vb[nj]);
            }
        }
        __syncthreads();
    }

    // ---- epilogue: normalize + write fp16 (lacc holds exact row sums) ----
    const float linv[2] = {1.0f / lacc[0], 1.0f / lacc[2]};
    #pragma unroll
    for (int half = 0; half < 2; ++half) {
        const int rloc = w * 16 + (lane >> 2) + half * 8;
        const size_t rg = (size_t)(b * SEQ + q0 + rloc) * 1024 + h * 64;
        const float inv = linv[half];
        #pragma unroll
        for (int nj = 0; nj < 8; ++nj) {
            const int col = nj * 8 + (lane & 3) * 2;
            const __half2 hv = __floats2half2_rn(o[nj][half * 2] * inv,
                                                 o[nj][half * 2 + 1] * inv);
            *reinterpret_cast<__half2*>(g_oh + rg + col) = hv;
        }
    }
}

// ---------------------------------------------------------------------------
// Inputs: x, start_pos, freqs_cos, freqs_sin, mask, wq, wk, wv, wo
// ---------------------------------------------------------------------------
extern "C" void kernel_launch(void* const* d_in, const int* in_sizes, int n_in,
                              void* d_out, int out_size)
{
    const float* x  = (const float*)d_in[0];
    const float* fc = (const float*)d_in[2];
    const float* fs = (const float*)d_in[3];
    const float* wq = (const float*)d_in[5];
    const float* wk = (const float*)d_in[6];
    const float* wv = (const float*)d_in[7];
    const float* wo = (const float*)d_in[8];
    float* out = (float*)d_out;

    cudaFuncSetAttribute(qkv_hmma_kernel,
                         cudaFuncAttributeMaxDynamicSharedMemorySize, GSM_TOT);
    cudaFuncSetAttribute(oproj_hmma_kernel,
                         cudaFuncAttributeMaxDynamicSharedMemorySize, GSM_TOT);
    cudaFuncSetAttribute(attn_mma_kernel,
                         cudaFuncAttributeMaxDynamicSharedMemorySize, ASM_TOT);

    // Fused prep (MLP=4): x -> fp16; weights -> transposed fp16
    prep_kernel<<<3584, 256>>>(x, wq, wk, wv, wo);
    // QKV projection (fp16 HMMA, 512 thr; Q/K RoPE'd fp16; V written transposed)
    qkv_hmma_kernel<<<dim3(12, 32), 512, GSM_TOT>>>(fc, fs);
    // Tensor-core flash attention (256 thr, 128-key stages)
    attn_mma_kernel<<<dim3(16, 16, 2), 256, ASM_TOT>>>();
    // Output projection -> d_out (fp32)
    oproj_hmma_kernel<<<dim3(8, 32), 512, GSM_TOT>>>(out);
}